// round 7
// baseline (speedup 1.0000x reference)
#include <cuda_runtime.h>
#include <cuda_bf16.h>
#include <math.h>
#include <stdint.h>

#define TLEN 32768
#define NB 2
#define RC 64
#define GC 128
#define SC 64
#define AC 80
#define NLAYERS 30
#define SQRT_HALF 0.70710678118654752440f
#define SQRT_INV_L 0.18257418583505537115f

// ======================= scratch (device globals) ============================
__device__ __align__(16) __nv_bfloat16 g_hHa[NB * TLEN * RC];
__device__ __align__(16) __nv_bfloat16 g_hLa[NB * TLEN * RC];
__device__ __align__(16) __nv_bfloat16 g_hHb[NB * TLEN * RC];
__device__ __align__(16) __nv_bfloat16 g_hLb[NB * TLEN * RC];
__device__ float g_skip[NB * TLEN * SC];
__device__ __align__(16) __nv_bfloat16 g_cPH[NB * 2 * TLEN * 64];
__device__ __align__(16) __nv_bfloat16 g_cPL[NB * 2 * TLEN * 64];
__device__ __align__(16) __nv_bfloat16 g_WgH[NLAYERS * 5 * 128 * 64];
__device__ __align__(16) __nv_bfloat16 g_WgL[NLAYERS * 5 * 128 * 64];
__device__ __align__(16) __nv_bfloat16 g_W2H[NLAYERS * 128 * 64];
__device__ __align__(16) __nv_bfloat16 g_W2L[NLAYERS * 128 * 64];

// ======================= helpers =============================================
__device__ __forceinline__ uint32_t smem_u32(const void* p) {
    uint32_t a;
    asm("{ .reg .u64 t; cvta.to.shared.u64 t, %1; cvt.u32.u64 %0, t; }" : "=r"(a) : "l"(p));
    return a;
}
__device__ __forceinline__ void ldm4(uint32_t* r, uint32_t addr) {
    asm volatile("ldmatrix.sync.aligned.m8n8.x4.shared.b16 {%0,%1,%2,%3}, [%4];"
        : "=r"(r[0]), "=r"(r[1]), "=r"(r[2]), "=r"(r[3]) : "r"(addr));
}
__device__ __forceinline__ void mma16816(float* d, const uint32_t* a, uint32_t b0, uint32_t b1) {
    asm volatile("mma.sync.aligned.m16n8k16.row.col.f32.bf16.bf16.f32 "
        "{%0,%1,%2,%3}, {%4,%5,%6,%7}, {%8,%9}, {%0,%1,%2,%3};"
        : "+f"(d[0]), "+f"(d[1]), "+f"(d[2]), "+f"(d[3])
        : "r"(a[0]), "r"(a[1]), "r"(a[2]), "r"(a[3]), "r"(b0), "r"(b1));
}
__device__ __forceinline__ void cpa16(uint32_t dst, const void* src, int srcsz) {
    asm volatile("cp.async.ca.shared.global [%0], [%1], 16, %2;"
        :: "r"(dst), "l"(src), "r"(srcsz) : "memory");
}
#define CP_COMMIT() asm volatile("cp.async.commit_group;" ::: "memory")
#define CP_WAIT0()  asm volatile("cp.async.wait_group 0;" ::: "memory")
#define CP_WAIT1()  asm volatile("cp.async.wait_group 1;" ::: "memory")

__device__ __forceinline__ uint32_t packbf2(float lo, float hi) {
    __nv_bfloat162 t = __floats2bfloat162_rn(lo, hi);
    return *(uint32_t*)&t;
}

// ======================= fused conditioning ==================================
__global__ void cond_fused(const float* __restrict__ c, const float* __restrict__ Wc,
                           const float* __restrict__ Wup,
                           __nv_bfloat16* __restrict__ PH, __nv_bfloat16* __restrict__ PL) {
    extern __shared__ float us[];
    const int b  = blockIdx.y;
    const int t0 = blockIdx.x * 128;
    const int tid = threadIdx.x;   // 256

    const int u0 = (t0 - 4) >> 2;
    const int un = ((t0 + 131) >> 2) - u0 + 1;
    const int v0 = (u0 - 4) >> 2;
    const int vn = ((u0 + un - 1 + 4) >> 2) - v0 + 1;
    const int w0 = (v0 - 4) >> 2;
    const int wn = ((v0 + vn - 1 + 4) >> 2) - w0 + 1;
    const int f0 = (w0 - 4) >> 2;
    const int fn = ((w0 + wn - 1 + 4) >> 2) - f0 + 1;

    float* y0 = us;
    float* y1 = y0 + 80 * 6;
    float* s1 = y1 + 80 * 8;
    float* s2 = s1 + 80 * 8;
    float* s3 = s2 + 80 * 14;
    float* s4 = s3 + 80 * 36;

    for (int i = tid; i < 80 * fn; i += 256) {
        int ch = i / fn, ff = i - ch * fn;
        int f = f0 + ff;
        y0[ch * 6 + ff] = (f >= 0 && f < 128) ? c[((size_t)b * 80 + ch) * 128 + f] : 0.f;
    }
    __syncthreads();
    for (int i = tid; i < 80 * fn; i += 256) {
        int o = i / fn, ff = i - o * fn;
        float acc = 0.f;
        #pragma unroll 4
        for (int k = 0; k < 80; ++k) acc += Wc[o * 80 + k] * y0[k * 6 + ff];
        y1[o * 8 + ff] = acc;
    }
    __syncthreads();
    for (int i = tid; i < 80 * wn; i += 256) {
        int o = i / wn, wi = i - o * wn;
        int w = w0 + wi;
        float acc = 0.f;
        #pragma unroll
        for (int k = 0; k < 9; ++k) {
            int rr = w - 4 + k;
            if (rr >= 0 && rr < 512) acc += Wup[k] * y1[o * 8 + ((rr >> 2) - f0)];
        }
        s1[o * 8 + wi] = acc;
    }
    __syncthreads();
    for (int i = tid; i < 80 * vn; i += 256) {
        int o = i / vn, vi = i - o * vn;
        int v = v0 + vi;
        float acc = 0.f;
        #pragma unroll
        for (int k = 0; k < 9; ++k) {
            int rr = v - 4 + k;
            if (rr >= 0 && rr < 2048) acc += Wup[9 + k] * s1[o * 8 + ((rr >> 2) - w0)];
        }
        s2[o * 14 + vi] = acc;
    }
    __syncthreads();
    for (int i = tid; i < 80 * un; i += 256) {
        int o = i / un, ui = i - o * un;
        int u = u0 + ui;
        float acc = 0.f;
        #pragma unroll
        for (int k = 0; k < 9; ++k) {
            int rr = u - 4 + k;
            if (rr >= 0 && rr < 8192) acc += Wup[18 + k] * s2[o * 14 + ((rr >> 2) - v0)];
        }
        s3[o * 36 + ui] = acc;
    }
    __syncthreads();
    for (int i = tid; i < 80 * 128; i += 256) {
        int o = i >> 7, tl = i & 127;
        int t = t0 + tl;
        float acc = 0.f;
        #pragma unroll
        for (int k = 0; k < 9; ++k) {
            int rr = t - 4 + k;
            if (rr >= 0 && rr < TLEN) acc += Wup[27 + k] * s3[o * 36 + ((rr >> 2) - u0)];
        }
        s4[o * 128 + tl] = acc;
    }
    __syncthreads();
    for (int i = tid; i < 128 * 64; i += 256) {
        int tl = i >> 6, j = i & 63;
        size_t o0 = (((size_t)b * 2 + 0) * TLEN + (t0 + tl)) * 64 + j;
        size_t o1 = (((size_t)b * 2 + 1) * TLEN + (t0 + tl)) * 64 + j;
        float v0f = s4[j * 128 + tl];
        float v1f = (j < 16) ? s4[(64 + j) * 128 + tl] : 0.f;
        __nv_bfloat16 h0 = __float2bfloat16(v0f);
        __nv_bfloat16 h1 = __float2bfloat16(v1f);
        PH[o0] = h0;  PL[o0] = __float2bfloat16(v0f - __bfloat162float(h0));
        PH[o1] = h1;  PL[o1] = __float2bfloat16(v1f - __bfloat162float(h1));
    }
}

// ======================= weight prepack ======================================
__global__ void prepack_w(const float* __restrict__ Wd, const float* __restrict__ Wa,
                          const float* __restrict__ Ws, const float* __restrict__ Wr,
                          __nv_bfloat16* __restrict__ WgH, __nv_bfloat16* __restrict__ WgL,
                          __nv_bfloat16* __restrict__ W2H, __nv_bfloat16* __restrict__ W2L) {
    const int N1 = NLAYERS * 5 * 128 * 64;
    const int N2 = NLAYERS * 128 * 64;
    int i = blockIdx.x * blockDim.x + threadIdx.x;
    if (i < N1) {
        int kl = i & 63;
        int r  = (i >> 6) & 127;
        int lc = i >> 13;
        int cc = lc % 5;
        int l  = lc / 5;
        int j  = ((r >> 4) << 3) + (((r & 7) >> 1) << 1) + ((r >> 3) & 1);
        int ch = (r & 1) ? (64 + j) : j;
        float w;
        if (cc < 3)       w = Wd[(((size_t)l * GC + ch) * RC + kl) * 3 + cc];
        else if (cc == 3) w = Wa[((size_t)l * GC + ch) * AC + kl];
        else              w = (kl < AC - 64) ? Wa[((size_t)l * GC + ch) * AC + 64 + kl] : 0.f;
        __nv_bfloat16 h = __float2bfloat16(w);
        WgH[i] = h;
        WgL[i] = __float2bfloat16(w - __bfloat162float(h));
    } else if (i - N1 < N2) {
        int i2 = i - N1;
        int k  = i2 & 63;
        int r2 = (i2 >> 6) & 127;
        int l  = i2 >> 13;
        float w = (r2 < 64) ? Ws[((size_t)l * SC + r2) * 64 + k]
                            : Wr[((size_t)l * RC + (r2 - 64)) * 64 + k];
        __nv_bfloat16 h = __float2bfloat16(w);
        W2H[i2] = h;
        W2L[i2] = __float2bfloat16(w - __bfloat162float(h));
    }
}

__global__ void first_pack(const float* __restrict__ x,
                           const float* __restrict__ Wf, const float* __restrict__ bf,
                           __nv_bfloat16* __restrict__ hH, __nv_bfloat16* __restrict__ hL,
                           float* __restrict__ skip) {
    int idx = blockIdx.x * blockDim.x + threadIdx.x;
    if (idx >= NB * TLEN * RC) return;
    int j = idx & 63;
    int t = (idx >> 6) & (TLEN - 1);
    int b = idx >> 21;
    float v = Wf[j] * x[(size_t)b * TLEN + t] + bf[j];
    __nv_bfloat16 h = __float2bfloat16(v);
    hH[idx] = h;
    hL[idx] = __float2bfloat16(v - __bfloat162float(h));
    skip[idx] = 0.f;
}

// ======================= fused residual layer ================================
// 8 double-buffered regions of 128 rows x 80B (32 bf16 + 16B pad):
//   W hi (x2), W lo (x2), D hi (x2), D lo (x2); biases after.
#define RSTRIDE 80
#define RSZ (128 * RSTRIDE)
#define OFF_WHB 0
#define OFF_WLB (2 * RSZ)
#define OFF_DHB (4 * RSZ)
#define OFF_DLB (6 * RSZ)
#define OFF_BD  (8 * RSZ)
#define SMEM_NEED (OFF_BD + 1024)

__global__ __launch_bounds__(256, 2)
void layer_mma(int l, int dil,
               const __nv_bfloat16* __restrict__ hinH, const __nv_bfloat16* __restrict__ hinL,
               __nv_bfloat16* __restrict__ houtH, __nv_bfloat16* __restrict__ houtL,
               const __nv_bfloat16* __restrict__ cPH, const __nv_bfloat16* __restrict__ cPL,
               float* __restrict__ skip,
               const __nv_bfloat16* __restrict__ WgH, const __nv_bfloat16* __restrict__ WgL,
               const __nv_bfloat16* __restrict__ W2H, const __nv_bfloat16* __restrict__ W2L,
               const float* __restrict__ bd, const float* __restrict__ bs,
               const float* __restrict__ br) {
    extern __shared__ char smem_c[];
    const uint32_t sb = smem_u32(smem_c);
    float* sbd = (float*)(smem_c + OFF_BD);

    const int tid  = threadIdx.x;
    const int warp = tid >> 5;
    const int lane = tid & 31;
    const int b    = blockIdx.y;
    const int t0   = blockIdx.x * 128;
    const int mbase = warp * 16;

    const int lrow  = lane & 15;
    const int lkoff = (lane >> 4) * 16;
    const int q     = lane & 3;
    const int r     = lane >> 2;

    // biases: bd[0..127], bs[128..191], br[192..255]
    if (tid < 128)      sbd[tid] = bd[l * GC + tid];
    else if (tid < 192) sbd[tid] = bs[l * SC + tid - 128];
    else                sbd[tid] = br[l * RC + tid - 192];

    // ---- pipelined staging: slot s ∈ [0,8] = GEMM1 32k-chunk (global chunk
    // C=s>>1, half h=s&1); slot 9/10 = W2 halves (into W buf 1/0). ----
    auto stage = [&](int s) {
        const int buf = s & 1;
        if (s <= 8) {
            const int C = s >> 1, h = s & 1;
            const char* wHb = (const char*)WgH + (((size_t)l * 5 + C) * 128) * 128;
            const char* wLb = (const char*)WgL + (((size_t)l * 5 + C) * 128) * 128;
            #pragma unroll
            for (int it = 0; it < 2; ++it) {
                const int p = it * 256 + tid;
                const int row = p >> 2, j = p & 3;
                const uint32_t d = (uint32_t)row * RSTRIDE + j * 16;
                const int go = row * 128 + h * 64 + j * 16;
                cpa16(sb + OFF_WHB + buf * RSZ + d, wHb + go, 16);
                cpa16(sb + OFF_WLB + buf * RSZ + d, wLb + go, 16);
                const char* sH; const char* sL; int sz = 16;
                if (C < 3) {
                    int tg = t0 + row + (C - 1) * dil;
                    if (tg >= 0 && tg < TLEN) {
                        size_t e = ((size_t)b * TLEN + tg) * 128 + h * 64 + j * 16;
                        sH = (const char*)hinH + e;
                        sL = (const char*)hinL + e;
                    } else { sH = (const char*)hinH; sL = (const char*)hinL; sz = 0; }
                } else {
                    size_t e = (((size_t)b * 2 + (C - 3)) * TLEN + (t0 + row)) * 128 + h * 64 + j * 16;
                    sH = (const char*)cPH + e;
                    sL = (const char*)cPL + e;
                }
                cpa16(sb + OFF_DHB + buf * RSZ + d, sH, sz);
                cpa16(sb + OFF_DLB + buf * RSZ + d, sL, sz);
            }
        } else {
            const int h = s - 9;
            const char* wHb = (const char*)W2H + (size_t)l * 128 * 128;
            const char* wLb = (const char*)W2L + (size_t)l * 128 * 128;
            #pragma unroll
            for (int it = 0; it < 2; ++it) {
                const int p = it * 256 + tid;
                const int row = p >> 2, j = p & 3;
                const uint32_t d = (uint32_t)row * RSTRIDE + j * 16;
                const int go = row * 128 + h * 64 + j * 16;
                cpa16(sb + OFF_WHB + buf * RSZ + d, wHb + go, 16);
                cpa16(sb + OFF_WLB + buf * RSZ + d, wLb + go, 16);
            }
        }
        CP_COMMIT();
    };

    stage(0);
    stage(1);

    float acc[16][4];
    #pragma unroll
    for (int i = 0; i < 16; ++i)
        #pragma unroll
        for (int j2 = 0; j2 < 4; ++j2) acc[i][j2] = 0.f;

    // ---------------- GEMM1 pipeline over 9 chunks ----------------
    for (int c = 0; c <= 8; ++c) {
        CP_WAIT1();
        __syncthreads();
        const int buf = c & 1;
        const int nks = (c == 8) ? 1 : 2;
        const uint32_t a_hi = sb + OFF_DHB + buf * RSZ + (uint32_t)(mbase + lrow) * RSTRIDE + lkoff;
        const uint32_t b_hi = sb + OFF_WHB + buf * RSZ + (uint32_t)lrow * RSTRIDE + lkoff;
        for (int ks = 0; ks < nks; ++ks) {
            uint32_t ah[4], al[4];
            ldm4(ah, a_hi + ks * 32);
            ldm4(al, a_hi + 2 * RSZ + ks * 32);
            #pragma unroll
            for (int g = 0; g < 2; ++g) {
                uint32_t bh[4][4], bl[4][4];
                #pragma unroll
                for (int i = 0; i < 4; ++i) {
                    uint32_t baddr = b_hi + (uint32_t)((g * 4 + i) * 16) * RSTRIDE + ks * 32;
                    ldm4(bh[i], baddr);
                    ldm4(bl[i], baddr + 2 * RSZ);
                }
                #pragma unroll
                for (int i = 0; i < 4; ++i) {
                    mma16816(acc[(g * 4 + i) * 2],     ah, bh[i][0], bh[i][2]);
                    mma16816(acc[(g * 4 + i) * 2 + 1], ah, bh[i][1], bh[i][3]);
                }
                #pragma unroll
                for (int i = 0; i < 4; ++i) {
                    mma16816(acc[(g * 4 + i) * 2],     ah, bl[i][0], bl[i][2]);
                    mma16816(acc[(g * 4 + i) * 2 + 1], ah, bl[i][1], bl[i][3]);
                }
                #pragma unroll
                for (int i = 0; i < 4; ++i) {
                    mma16816(acc[(g * 4 + i) * 2],     al, bh[i][0], bh[i][2]);
                    mma16816(acc[(g * 4 + i) * 2 + 1], al, bh[i][1], bh[i][3]);
                }
            }
        }
        __syncthreads();
        stage(c + 2);   // slots 2..10 (9/10 = W2 halves)
    }

    // ---------------- gate (registers only) ----------------
    uint32_t zhA[8], zlA[8], zhB[8], zlB[8];
    #pragma unroll
    for (int nt = 0; nt < 8; ++nt) {
        float zA[2], zB[2];
        #pragma unroll
        for (int s = 0; s < 2; ++s) {
            int j = nt * 8 + 2 * q + s;
            float ba = sbd[j], bb = sbd[64 + j];
            #pragma unroll
            for (int h = 0; h < 2; ++h) {
                float xa = acc[nt * 2 + s][h * 2 + 0] + ba;
                float xb = acc[nt * 2 + s][h * 2 + 1] + bb;
                float e2 = __expf(-2.f * fabsf(xa));
                float th = copysignf(__fdividef(1.f - e2, 1.f + e2), xa);
                float sg = __fdividef(1.f, 1.f + __expf(-xb));
                float z = th * sg;
                if (h == 0) zA[s] = z; else zB[s] = z;
            }
        }
        zhA[nt] = packbf2(zA[0], zA[1]);
        zhB[nt] = packbf2(zB[0], zB[1]);
        __nv_bfloat162 hA = *(__nv_bfloat162*)&zhA[nt];
        __nv_bfloat162 hB = *(__nv_bfloat162*)&zhB[nt];
        zlA[nt] = packbf2(zA[0] - __bfloat162float(hA.x), zA[1] - __bfloat162float(hA.y));
        zlB[nt] = packbf2(zB[0] - __bfloat162float(hB.x), zB[1] - __bfloat162float(hB.y));
    }

    CP_WAIT0();
    __syncthreads();

    // ---------------- GEMM2: z(t x 64) * W2^T; W2 ks0,1 in buf1, ks2,3 in buf0
    float acc2[16][4];
    #pragma unroll
    for (int i = 0; i < 16; ++i)
        #pragma unroll
        for (int j2 = 0; j2 < 4; ++j2) acc2[i][j2] = 0.f;

    #pragma unroll
    for (int ks = 0; ks < 4; ++ks) {
        const int buf = (ks < 2) ? 1 : 0;
        const int col = (ks & 1) * 32;
        uint32_t azh[4] = {zhA[2 * ks], zhB[2 * ks], zhA[2 * ks + 1], zhB[2 * ks + 1]};
        uint32_t azl[4] = {zlA[2 * ks], zlB[2 * ks], zlA[2 * ks + 1], zlB[2 * ks + 1]};
        const uint32_t b_hi = sb + OFF_WHB + buf * RSZ + (uint32_t)lrow * RSTRIDE + lkoff + col;
        #pragma unroll
        for (int g = 0; g < 2; ++g) {
            uint32_t wh[4][4], wl[4][4];
            #pragma unroll
            for (int i = 0; i < 4; ++i) {
                uint32_t baddr = b_hi + (uint32_t)((g * 4 + i) * 16) * RSTRIDE;
                ldm4(wh[i], baddr);
                ldm4(wl[i], baddr + 2 * RSZ);
            }
            #pragma unroll
            for (int i = 0; i < 4; ++i) {
                mma16816(acc2[(g * 4 + i) * 2],     azh, wh[i][0], wh[i][2]);
                mma16816(acc2[(g * 4 + i) * 2 + 1], azh, wh[i][1], wh[i][3]);
            }
            #pragma unroll
            for (int i = 0; i < 4; ++i) {
                mma16816(acc2[(g * 4 + i) * 2],     azh, wl[i][0], wl[i][2]);
                mma16816(acc2[(g * 4 + i) * 2 + 1], azh, wl[i][1], wl[i][3]);
            }
            #pragma unroll
            for (int i = 0; i < 4; ++i) {
                mma16816(acc2[(g * 4 + i) * 2],     azl, wh[i][0], wh[i][2]);
                mma16816(acc2[(g * 4 + i) * 2 + 1], azl, wh[i][1], wh[i][3]);
            }
        }
    }

    // ---------------- epilogue (coalesced [t][ch]) ----------------
    const int trowA = t0 + mbase + r;
    const int trowB = trowA + 8;
    #pragma unroll
    for (int nt = 0; nt < 8; ++nt) {
        #pragma unroll
        for (int s = 0; s < 2; ++s) {
            int cch = nt * 16 + s * 8 + 2 * q;
            float d0 = acc2[nt * 2 + s][0], d1 = acc2[nt * 2 + s][1];
            float d2 = acc2[nt * 2 + s][2], d3 = acc2[nt * 2 + s][3];
            if (cch < 64) {
                float bs0 = sbd[128 + cch], bs1 = sbd[128 + cch + 1];
                float2* p1 = (float2*)&skip[((size_t)b * TLEN + trowA) * 64 + cch];
                float2* p2 = (float2*)&skip[((size_t)b * TLEN + trowB) * 64 + cch];
                float2 v1 = *p1, v2 = *p2;
                v1.x += d0 + bs0; v1.y += d1 + bs1;
                v2.x += d2 + bs0; v2.y += d3 + bs1;
                *p1 = v1; *p2 = v2;
            } else {
                int ch = cch - 64;
                float br0 = sbd[192 + ch], br1 = sbd[192 + ch + 1];
                size_t e1 = ((size_t)b * TLEN + trowA) * 64 + ch;
                size_t e2 = ((size_t)b * TLEN + trowB) * 64 + ch;
                __nv_bfloat162 iH1 = *(__nv_bfloat162*)&hinH[e1];
                __nv_bfloat162 iL1 = *(__nv_bfloat162*)&hinL[e1];
                __nv_bfloat162 iH2 = *(__nv_bfloat162*)&hinH[e2];
                __nv_bfloat162 iL2 = *(__nv_bfloat162*)&hinL[e2];
                float h10 = (d0 + br0 + __bfloat162float(iH1.x) + __bfloat162float(iL1.x)) * SQRT_HALF;
                float h11 = (d1 + br1 + __bfloat162float(iH1.y) + __bfloat162float(iL1.y)) * SQRT_HALF;
                float h20 = (d2 + br0 + __bfloat162float(iH2.x) + __bfloat162float(iL2.x)) * SQRT_HALF;
                float h21 = (d3 + br1 + __bfloat162float(iH2.y) + __bfloat162float(iL2.y)) * SQRT_HALF;
                uint32_t oh1 = packbf2(h10, h11);
                uint32_t oh2 = packbf2(h20, h21);
                __nv_bfloat162 hh1 = *(__nv_bfloat162*)&oh1;
                __nv_bfloat162 hh2 = *(__nv_bfloat162*)&oh2;
                uint32_t ol1 = packbf2(h10 - __bfloat162float(hh1.x), h11 - __bfloat162float(hh1.y));
                uint32_t ol2 = packbf2(h20 - __bfloat162float(hh2.x), h21 - __bfloat162float(hh2.y));
                *(uint32_t*)&houtH[e1] = oh1;
                *(uint32_t*)&houtL[e1] = ol1;
                *(uint32_t*)&houtH[e2] = oh2;
                *(uint32_t*)&houtL[e2] = ol2;
            }
        }
    }
}

// ======================= final head ==========================================
__global__ void final2(const float* __restrict__ skip,
                       const float* __restrict__ Wl1, const float* __restrict__ bl1,
                       const float* __restrict__ Wl2, const float* __restrict__ bl2,
                       float* __restrict__ out) {
    __shared__ float tile[128 * 65];
    __shared__ float b1s[64];
    __shared__ float W2s[64];
    int tid = threadIdx.x;   // 128
    if (tid < 64) { b1s[tid] = bl1[tid]; W2s[tid] = Wl2[tid]; }
    int t0 = (blockIdx.x & 255) * 128;
    int b  = blockIdx.x >> 8;
    for (int i = tid; i < 128 * 64; i += 128) {
        int rr = i >> 6, cc = i & 63;
        tile[rr * 65 + cc] = skip[((size_t)b * TLEN + t0) * 64 + i];
    }
    __syncthreads();
    float s1[64];
    #pragma unroll 8
    for (int j = 0; j < 64; ++j)
        s1[j] = fmaxf(tile[tid * 65 + j] * SQRT_INV_L, 0.f);
    float y2 = bl2[0];
    for (int o = 0; o < 64; ++o) {
        float a = b1s[o];
        #pragma unroll 8
        for (int j = 0; j < 64; ++j) a += Wl1[o * 64 + j] * s1[j];
        y2 += W2s[o] * fmaxf(a, 0.f);
    }
    out[(size_t)b * TLEN + t0 + tid] = y2;
}

// ======================= launch ==============================================
extern "C" void kernel_launch(void* const* d_in, const int* in_sizes, int n_in,
                              void* d_out, int out_size)
{
    const float* x       = (const float*)d_in[0];
    const float* c       = (const float*)d_in[1];
    const float* W_first = (const float*)d_in[2];
    const float* b_first = (const float*)d_in[3];
    const float* W_cin   = (const float*)d_in[4];
    const float* W_up    = (const float*)d_in[5];
    const float* Wd      = (const float*)d_in[6];
    const float* bd      = (const float*)d_in[7];
    const float* Wa      = (const float*)d_in[8];
    const float* Ws      = (const float*)d_in[9];
    const float* bs      = (const float*)d_in[10];
    const float* Wr      = (const float*)d_in[11];
    const float* br      = (const float*)d_in[12];
    const float* Wl1     = (const float*)d_in[13];
    const float* bl1     = (const float*)d_in[14];
    const float* Wl2     = (const float*)d_in[15];
    const float* bl2     = (const float*)d_in[16];
    float* out = (float*)d_out;

    float *skip;
    __nv_bfloat16 *hHa, *hLa, *hHb, *hLb, *cPH, *cPL, *WgH, *WgL, *W2H, *W2L;
    cudaGetSymbolAddress((void**)&skip, g_skip);
    cudaGetSymbolAddress((void**)&hHa,  g_hHa);
    cudaGetSymbolAddress((void**)&hLa,  g_hLa);
    cudaGetSymbolAddress((void**)&hHb,  g_hHb);
    cudaGetSymbolAddress((void**)&hLb,  g_hLb);
    cudaGetSymbolAddress((void**)&cPH,  g_cPH);
    cudaGetSymbolAddress((void**)&cPL,  g_cPL);
    cudaGetSymbolAddress((void**)&WgH,  g_WgH);
    cudaGetSymbolAddress((void**)&WgL,  g_WgL);
    cudaGetSymbolAddress((void**)&W2H,  g_W2H);
    cudaGetSymbolAddress((void**)&W2L,  g_W2L);

    const int COND_SMEM = (80 * 6 + 80 * 8 + 80 * 8 + 80 * 14 + 80 * 36 + 80 * 128) * 4;
    cudaFuncSetAttribute(cond_fused, cudaFuncAttributeMaxDynamicSharedMemorySize, COND_SMEM);
    cudaFuncSetAttribute(layer_mma, cudaFuncAttributeMaxDynamicSharedMemorySize, SMEM_NEED);

    {
        dim3 grid(TLEN / 128, NB);
        cond_fused<<<grid, 256, COND_SMEM>>>(c, W_cin, W_up, cPH, cPL);
    }
    {
        int N = NLAYERS * 5 * 128 * 64 + NLAYERS * 128 * 64;
        prepack_w<<<(N + 255) / 256, 256>>>(Wd, Wa, Ws, Wr, WgH, WgL, W2H, W2L);
    }
    {
        int N = NB * TLEN * RC;
        first_pack<<<(N + 255) / 256, 256>>>(x, W_first, b_first, hHa, hLa, skip);
    }
    __nv_bfloat16 *hiH = hHa, *hiL = hLa, *hoH = hHb, *hoL = hLb;
    dim3 grid(TLEN / 128, NB);
    for (int i = 0; i < NLAYERS; ++i) {
        int d = 1 << (i % 10);
        layer_mma<<<grid, 256, SMEM_NEED>>>(i, d, hiH, hiL, hoH, hoL,
                                            cPH, cPL, skip, WgH, WgL, W2H, W2L, bd, bs, br);
        { __nv_bfloat16* t = hiH; hiH = hoH; hoH = t; }
        { __nv_bfloat16* t = hiL; hiL = hoL; hoL = t; }
    }
    final2<<<NB * (TLEN / 128), 128>>>(skip, Wl1, bl1, Wl2, bl2, out);
}

// round 8
// speedup vs baseline: 1.0022x; 1.0022x over previous
#include <cuda_runtime.h>
#include <cuda_bf16.h>
#include <math.h>
#include <stdint.h>

#define TLEN 32768
#define NB 2
#define RC 64
#define GC 128
#define SC 64
#define AC 80
#define NLAYERS 30
#define SQRT_HALF 0.70710678118654752440f
#define SQRT_INV_L 0.18257418583505537115f

// ======================= scratch (device globals) ============================
__device__ __align__(16) __nv_bfloat16 g_hHa[NB * TLEN * RC];
__device__ __align__(16) __nv_bfloat16 g_hLa[NB * TLEN * RC];
__device__ __align__(16) __nv_bfloat16 g_hHb[NB * TLEN * RC];
__device__ __align__(16) __nv_bfloat16 g_hLb[NB * TLEN * RC];
__device__ float g_skip[NB * TLEN * SC];
__device__ __align__(16) __nv_bfloat16 g_cPH[NB * 2 * TLEN * 64];
__device__ __align__(16) __nv_bfloat16 g_cPL[NB * 2 * TLEN * 64];
__device__ __align__(16) __nv_bfloat16 g_WgH[NLAYERS * 5 * 128 * 64];
__device__ __align__(16) __nv_bfloat16 g_WgL[NLAYERS * 5 * 128 * 64];
__device__ __align__(16) __nv_bfloat16 g_W2H[NLAYERS * 128 * 64];
__device__ __align__(16) __nv_bfloat16 g_W2L[NLAYERS * 128 * 64];

// ======================= helpers =============================================
__device__ __forceinline__ uint32_t smem_u32(const void* p) {
    uint32_t a;
    asm("{ .reg .u64 t; cvta.to.shared.u64 t, %1; cvt.u32.u64 %0, t; }" : "=r"(a) : "l"(p));
    return a;
}
__device__ __forceinline__ void ldm4(uint32_t* r, uint32_t addr) {
    asm volatile("ldmatrix.sync.aligned.m8n8.x4.shared.b16 {%0,%1,%2,%3}, [%4];"
        : "=r"(r[0]), "=r"(r[1]), "=r"(r[2]), "=r"(r[3]) : "r"(addr));
}
__device__ __forceinline__ void mma16816(float* d, const uint32_t* a, uint32_t b0, uint32_t b1) {
    asm volatile("mma.sync.aligned.m16n8k16.row.col.f32.bf16.bf16.f32 "
        "{%0,%1,%2,%3}, {%4,%5,%6,%7}, {%8,%9}, {%0,%1,%2,%3};"
        : "+f"(d[0]), "+f"(d[1]), "+f"(d[2]), "+f"(d[3])
        : "r"(a[0]), "r"(a[1]), "r"(a[2]), "r"(a[3]), "r"(b0), "r"(b1));
}
__device__ __forceinline__ void cpa16(uint32_t dst, const void* src, int srcsz) {
    asm volatile("cp.async.ca.shared.global [%0], [%1], 16, %2;"
        :: "r"(dst), "l"(src), "r"(srcsz) : "memory");
}
#define CP_COMMIT() asm volatile("cp.async.commit_group;" ::: "memory")
#define CP_WAIT0()  asm volatile("cp.async.wait_group 0;" ::: "memory")

__device__ __forceinline__ uint32_t packbf2(float lo, float hi) {
    __nv_bfloat162 t = __floats2bfloat162_rn(lo, hi);
    return *(uint32_t*)&t;
}

// ======================= fused conditioning ==================================
__global__ void cond_fused(const float* __restrict__ c, const float* __restrict__ Wc,
                           const float* __restrict__ Wup,
                           __nv_bfloat16* __restrict__ PH, __nv_bfloat16* __restrict__ PL) {
    extern __shared__ float us[];
    const int b  = blockIdx.y;
    const int t0 = blockIdx.x * 128;
    const int tid = threadIdx.x;   // 256

    const int u0 = (t0 - 4) >> 2;
    const int un = ((t0 + 131) >> 2) - u0 + 1;
    const int v0 = (u0 - 4) >> 2;
    const int vn = ((u0 + un - 1 + 4) >> 2) - v0 + 1;
    const int w0 = (v0 - 4) >> 2;
    const int wn = ((v0 + vn - 1 + 4) >> 2) - w0 + 1;
    const int f0 = (w0 - 4) >> 2;
    const int fn = ((w0 + wn - 1 + 4) >> 2) - f0 + 1;

    float* y0 = us;
    float* y1 = y0 + 80 * 6;
    float* s1 = y1 + 80 * 8;
    float* s2 = s1 + 80 * 8;
    float* s3 = s2 + 80 * 14;
    float* s4 = s3 + 80 * 36;

    for (int i = tid; i < 80 * fn; i += 256) {
        int ch = i / fn, ff = i - ch * fn;
        int f = f0 + ff;
        y0[ch * 6 + ff] = (f >= 0 && f < 128) ? c[((size_t)b * 80 + ch) * 128 + f] : 0.f;
    }
    __syncthreads();
    for (int i = tid; i < 80 * fn; i += 256) {
        int o = i / fn, ff = i - o * fn;
        float acc = 0.f;
        #pragma unroll 4
        for (int k = 0; k < 80; ++k) acc += Wc[o * 80 + k] * y0[k * 6 + ff];
        y1[o * 8 + ff] = acc;
    }
    __syncthreads();
    for (int i = tid; i < 80 * wn; i += 256) {
        int o = i / wn, wi = i - o * wn;
        int w = w0 + wi;
        float acc = 0.f;
        #pragma unroll
        for (int k = 0; k < 9; ++k) {
            int rr = w - 4 + k;
            if (rr >= 0 && rr < 512) acc += Wup[k] * y1[o * 8 + ((rr >> 2) - f0)];
        }
        s1[o * 8 + wi] = acc;
    }
    __syncthreads();
    for (int i = tid; i < 80 * vn; i += 256) {
        int o = i / vn, vi = i - o * vn;
        int v = v0 + vi;
        float acc = 0.f;
        #pragma unroll
        for (int k = 0; k < 9; ++k) {
            int rr = v - 4 + k;
            if (rr >= 0 && rr < 2048) acc += Wup[9 + k] * s1[o * 8 + ((rr >> 2) - w0)];
        }
        s2[o * 14 + vi] = acc;
    }
    __syncthreads();
    for (int i = tid; i < 80 * un; i += 256) {
        int o = i / un, ui = i - o * un;
        int u = u0 + ui;
        float acc = 0.f;
        #pragma unroll
        for (int k = 0; k < 9; ++k) {
            int rr = u - 4 + k;
            if (rr >= 0 && rr < 8192) acc += Wup[18 + k] * s2[o * 14 + ((rr >> 2) - v0)];
        }
        s3[o * 36 + ui] = acc;
    }
    __syncthreads();
    for (int i = tid; i < 80 * 128; i += 256) {
        int o = i >> 7, tl = i & 127;
        int t = t0 + tl;
        float acc = 0.f;
        #pragma unroll
        for (int k = 0; k < 9; ++k) {
            int rr = t - 4 + k;
            if (rr >= 0 && rr < TLEN) acc += Wup[27 + k] * s3[o * 36 + ((rr >> 2) - u0)];
        }
        s4[o * 128 + tl] = acc;
    }
    __syncthreads();
    for (int i = tid; i < 128 * 64; i += 256) {
        int tl = i >> 6, j = i & 63;
        size_t o0 = (((size_t)b * 2 + 0) * TLEN + (t0 + tl)) * 64 + j;
        size_t o1 = (((size_t)b * 2 + 1) * TLEN + (t0 + tl)) * 64 + j;
        float v0f = s4[j * 128 + tl];
        float v1f = (j < 16) ? s4[(64 + j) * 128 + tl] : 0.f;
        __nv_bfloat16 h0 = __float2bfloat16(v0f);
        __nv_bfloat16 h1 = __float2bfloat16(v1f);
        PH[o0] = h0;  PL[o0] = __float2bfloat16(v0f - __bfloat162float(h0));
        PH[o1] = h1;  PL[o1] = __float2bfloat16(v1f - __bfloat162float(h1));
    }
}

// ======================= weight prepack ======================================
__global__ void prepack_w(const float* __restrict__ Wd, const float* __restrict__ Wa,
                          const float* __restrict__ Ws, const float* __restrict__ Wr,
                          __nv_bfloat16* __restrict__ WgH, __nv_bfloat16* __restrict__ WgL,
                          __nv_bfloat16* __restrict__ W2H, __nv_bfloat16* __restrict__ W2L) {
    const int N1 = NLAYERS * 5 * 128 * 64;
    const int N2 = NLAYERS * 128 * 64;
    int i = blockIdx.x * blockDim.x + threadIdx.x;
    if (i < N1) {
        int kl = i & 63;
        int r  = (i >> 6) & 127;
        int lc = i >> 13;
        int cc = lc % 5;
        int l  = lc / 5;
        int j  = ((r >> 4) << 3) + (((r & 7) >> 1) << 1) + ((r >> 3) & 1);
        int ch = (r & 1) ? (64 + j) : j;
        float w;
        if (cc < 3)       w = Wd[(((size_t)l * GC + ch) * RC + kl) * 3 + cc];
        else if (cc == 3) w = Wa[((size_t)l * GC + ch) * AC + kl];
        else              w = (kl < AC - 64) ? Wa[((size_t)l * GC + ch) * AC + 64 + kl] : 0.f;
        __nv_bfloat16 h = __float2bfloat16(w);
        WgH[i] = h;
        WgL[i] = __float2bfloat16(w - __bfloat162float(h));
    } else if (i - N1 < N2) {
        int i2 = i - N1;
        int k  = i2 & 63;
        int r2 = (i2 >> 6) & 127;
        int l  = i2 >> 13;
        float w = (r2 < 64) ? Ws[((size_t)l * SC + r2) * 64 + k]
                            : Wr[((size_t)l * RC + (r2 - 64)) * 64 + k];
        __nv_bfloat16 h = __float2bfloat16(w);
        W2H[i2] = h;
        W2L[i2] = __float2bfloat16(w - __bfloat162float(h));
    }
}

__global__ void first_pack(const float* __restrict__ x,
                           const float* __restrict__ Wf, const float* __restrict__ bf,
                           __nv_bfloat16* __restrict__ hH, __nv_bfloat16* __restrict__ hL,
                           float* __restrict__ skip) {
    int idx = blockIdx.x * blockDim.x + threadIdx.x;
    if (idx >= NB * TLEN * RC) return;
    int j = idx & 63;
    int t = (idx >> 6) & (TLEN - 1);
    int b = idx >> 21;
    float v = Wf[j] * x[(size_t)b * TLEN + t] + bf[j];
    __nv_bfloat16 h = __float2bfloat16(v);
    hH[idx] = h;
    hL[idx] = __float2bfloat16(v - __bfloat162float(h));
    skip[idx] = 0.f;
}

// ======================= fused residual layer ================================
// smem: 4 regions of 128 rows x 144B. W hi/lo = weights; D hi/lo = data, then z.
#define STRIDE 144
#define OFF_WH  0
#define OFF_WL  (128 * STRIDE)
#define OFF_DH  (2 * 128 * STRIDE)
#define OFF_DL  (3 * 128 * STRIDE)
#define OFF_BD  (4 * 128 * STRIDE)
#define SMEM_NEED (OFF_BD + 1024)

__global__ __launch_bounds__(256, 2)
void layer_mma(int l, int dil,
               const __nv_bfloat16* __restrict__ hinH, const __nv_bfloat16* __restrict__ hinL,
               __nv_bfloat16* __restrict__ houtH, __nv_bfloat16* __restrict__ houtL,
               const __nv_bfloat16* __restrict__ cPH, const __nv_bfloat16* __restrict__ cPL,
               float* __restrict__ skip,
               const __nv_bfloat16* __restrict__ WgH, const __nv_bfloat16* __restrict__ WgL,
               const __nv_bfloat16* __restrict__ W2H, const __nv_bfloat16* __restrict__ W2L,
               const float* __restrict__ bd, const float* __restrict__ bs,
               const float* __restrict__ br) {
    extern __shared__ char smem_c[];
    const uint32_t sb = smem_u32(smem_c);
    float* sbd = (float*)(smem_c + OFF_BD);

    const int tid  = threadIdx.x;
    const int warp = tid >> 5;
    const int lane = tid & 31;
    const int b    = blockIdx.y;
    const int t0   = blockIdx.x * 128;

    const int wm    = warp & 3;       // t-tile (32 rows)
    const int wn    = warp >> 2;      // n-tile (64 cols)
    const int mbase = wm * 32;
    const int nbase = wn * 64;

    const int lrow  = lane & 15;
    const int lkoff = (lane >> 4) * 16;
    const int q     = lane & 3;
    const int r     = lane >> 2;

    // biases: bd[0..127], bs[128..191], br[192..255]
    if (tid < 128)      sbd[tid] = bd[l * GC + tid];
    else if (tid < 192) sbd[tid] = bs[l * SC + tid - 128];
    else                sbd[tid] = br[l * RC + tid - 192];

    // ---- chunk staging via cp.async (R6-proven) ----
    auto stage_chunk = [&](int c) {
        const char* wHb = (const char*)(WgH + (((size_t)l * 5 + c) * 128) * 64);
        const char* wLb = (const char*)(WgL + (((size_t)l * 5 + c) * 128) * 64);
        #pragma unroll
        for (int it = 0; it < 4; ++it) {
            const int p = it * 256 + tid;
            const int row = p >> 3, j = p & 7;
            if (c == 4 && j >= 2) continue;
            const uint32_t d = (uint32_t)row * STRIDE + j * 16;
            cpa16(sb + OFF_WH + d, wHb + p * 16, 16);
            cpa16(sb + OFF_WL + d, wLb + p * 16, 16);
            const char* srcH;
            const char* srcL;
            int sz = 16;
            if (c < 3) {
                int tg = t0 + row + (c - 1) * dil;
                if (tg >= 0 && tg < TLEN) {
                    size_t e = ((size_t)b * TLEN + tg) * 128 + j * 16;
                    srcH = (const char*)hinH + e;
                    srcL = (const char*)hinL + e;
                } else { srcH = (const char*)hinH; srcL = (const char*)hinL; sz = 0; }
            } else {
                size_t e = (((size_t)b * 2 + (c - 3)) * TLEN + (t0 + row)) * 128 + j * 16;
                srcH = (const char*)cPH + e;
                srcL = (const char*)cPL + e;
            }
            cpa16(sb + OFF_DH + d, srcH, sz);
            cpa16(sb + OFF_DL + d, srcL, sz);
        }
        CP_COMMIT();
    };

    stage_chunk(0);

    // 16 accumulators: index = (mf*4 + i)*2 + p   (mf: m16-frag, i: n16-tile, p: n8)
    float acc[16][4];
    #pragma unroll
    for (int i = 0; i < 16; ++i)
        #pragma unroll
        for (int j2 = 0; j2 < 4; ++j2) acc[i][j2] = 0.f;

    // ---------------- GEMM1: D1[t 32][gch 64] per warp ----------------
    for (int c = 0; c < 5; ++c) {
        CP_WAIT0();
        __syncthreads();
        const int nks = (c == 4) ? 1 : 4;
        for (int ks = 0; ks < nks; ++ks) {
            uint32_t ah0[4], ah1[4], al0[4], al1[4];
            const uint32_t a0 = sb + (uint32_t)(mbase + lrow) * STRIDE + lkoff + ks * 32;
            const uint32_t a1 = a0 + 16 * STRIDE;
            ldm4(ah0, a0 + OFF_DH);
            ldm4(ah1, a1 + OFF_DH);
            ldm4(al0, a0 + OFF_DL);
            ldm4(al1, a1 + OFF_DL);
            uint32_t bh[4][4], bl[4][4];
            #pragma unroll
            for (int i = 0; i < 4; ++i) {
                uint32_t baddr = sb + (uint32_t)(nbase + i * 16 + lrow) * STRIDE + lkoff + ks * 32;
                ldm4(bh[i], baddr + OFF_WH);
                ldm4(bl[i], baddr + OFF_WL);
            }
            // hh sweep
            #pragma unroll
            for (int i = 0; i < 4; ++i) {
                mma16816(acc[i * 2],           ah0, bh[i][0], bh[i][2]);
                mma16816(acc[i * 2 + 1],       ah0, bh[i][1], bh[i][3]);
            }
            #pragma unroll
            for (int i = 0; i < 4; ++i) {
                mma16816(acc[8 + i * 2],       ah1, bh[i][0], bh[i][2]);
                mma16816(acc[8 + i * 2 + 1],   ah1, bh[i][1], bh[i][3]);
            }
            // hl sweep
            #pragma unroll
            for (int i = 0; i < 4; ++i) {
                mma16816(acc[i * 2],           ah0, bl[i][0], bl[i][2]);
                mma16816(acc[i * 2 + 1],       ah0, bl[i][1], bl[i][3]);
            }
            #pragma unroll
            for (int i = 0; i < 4; ++i) {
                mma16816(acc[8 + i * 2],       ah1, bl[i][0], bl[i][2]);
                mma16816(acc[8 + i * 2 + 1],   ah1, bl[i][1], bl[i][3]);
            }
            // lh sweep
            #pragma unroll
            for (int i = 0; i < 4; ++i) {
                mma16816(acc[i * 2],           al0, bh[i][0], bh[i][2]);
                mma16816(acc[i * 2 + 1],       al0, bh[i][1], bh[i][3]);
            }
            #pragma unroll
            for (int i = 0; i < 4; ++i) {
                mma16816(acc[8 + i * 2],       al1, bh[i][0], bh[i][2]);
                mma16816(acc[8 + i * 2 + 1],   al1, bh[i][1], bh[i][3]);
            }
        }
        __syncthreads();
        if (c < 4) stage_chunk(c + 1);
    }

    // stage W2 into W region (overlaps gate)
    {
        const char* wHb = (const char*)(W2H + (size_t)l * 128 * 64);
        const char* wLb = (const char*)(W2L + (size_t)l * 128 * 64);
        #pragma unroll
        for (int it = 0; it < 4; ++it) {
            const int p = it * 256 + tid;
            const int row = p >> 3, j = p & 7;
            const uint32_t d = (uint32_t)row * STRIDE + j * 16;
            cpa16(sb + OFF_WH + d, wHb + p * 16, 16);
            cpa16(sb + OFF_WL + d, wLb + p * 16, 16);
        }
        CP_COMMIT();
    }

    // ---------------- gate -> z into D region (smem, bf16 hi/lo) -------------
    #pragma unroll
    for (int mf = 0; mf < 2; ++mf) {
        const int tr0 = mbase + mf * 16 + r;
        #pragma unroll
        for (int i = 0; i < 4; ++i) {
            #pragma unroll
            for (int p = 0; p < 2; ++p) {
                const int j = (wn * 4 + i) * 8 + 2 * q + p;
                const float ba = sbd[j], bb = sbd[64 + j];
                const float* a = acc[(mf * 4 + i) * 2 + p];
                #pragma unroll
                for (int h = 0; h < 2; ++h) {
                    float xa = a[h * 2 + 0] + ba;
                    float xb = a[h * 2 + 1] + bb;
                    float e2 = __expf(-2.f * fabsf(xa));
                    float th = copysignf(__fdividef(1.f - e2, 1.f + e2), xa);
                    float sg = __fdividef(1.f, 1.f + __expf(-xb));
                    float z  = th * sg;
                    const int tr = tr0 + h * 8;
                    const uint32_t d = (uint32_t)tr * STRIDE + j * 2;
                    __nv_bfloat16 zh = __float2bfloat16(z);
                    *(__nv_bfloat16*)(smem_c + OFF_DH + d) = zh;
                    *(__nv_bfloat16*)(smem_c + OFF_DL + d) =
                        __float2bfloat16(z - __bfloat162float(zh));
                }
            }
        }
    }

    CP_WAIT0();
    __syncthreads();

    // ---------------- GEMM2: D2[t 32][och 64] = z * W2^T ----------------
    float acc2[16][4];
    #pragma unroll
    for (int i = 0; i < 16; ++i)
        #pragma unroll
        for (int j2 = 0; j2 < 4; ++j2) acc2[i][j2] = 0.f;

    #pragma unroll
    for (int ks = 0; ks < 4; ++ks) {
        uint32_t ah0[4], ah1[4], al0[4], al1[4];
        const uint32_t a0 = sb + (uint32_t)(mbase + lrow) * STRIDE + lkoff + ks * 32;
        const uint32_t a1 = a0 + 16 * STRIDE;
        ldm4(ah0, a0 + OFF_DH);
        ldm4(ah1, a1 + OFF_DH);
        ldm4(al0, a0 + OFF_DL);
        ldm4(al1, a1 + OFF_DL);
        uint32_t wh[4][4], wl[4][4];
        #pragma unroll
        for (int i = 0; i < 4; ++i) {
            uint32_t baddr = sb + (uint32_t)(nbase + i * 16 + lrow) * STRIDE + lkoff + ks * 32;
            ldm4(wh[i], baddr + OFF_WH);
            ldm4(wl[i], baddr + OFF_WL);
        }
        #pragma unroll
        for (int i = 0; i < 4; ++i) {
            mma16816(acc2[i * 2],         ah0, wh[i][0], wh[i][2]);
            mma16816(acc2[i * 2 + 1],     ah0, wh[i][1], wh[i][3]);
        }
        #pragma unroll
        for (int i = 0; i < 4; ++i) {
            mma16816(acc2[8 + i * 2],     ah1, wh[i][0], wh[i][2]);
            mma16816(acc2[8 + i * 2 + 1], ah1, wh[i][1], wh[i][3]);
        }
        #pragma unroll
        for (int i = 0; i < 4; ++i) {
            mma16816(acc2[i * 2],         ah0, wl[i][0], wl[i][2]);
            mma16816(acc2[i * 2 + 1],     ah0, wl[i][1], wl[i][3]);
        }
        #pragma unroll
        for (int i = 0; i < 4; ++i) {
            mma16816(acc2[8 + i * 2],     ah1, wl[i][0], wl[i][2]);
            mma16816(acc2[8 + i * 2 + 1], ah1, wl[i][1], wl[i][3]);
        }
        #pragma unroll
        for (int i = 0; i < 4; ++i) {
            mma16816(acc2[i * 2],         al0, wh[i][0], wh[i][2]);
            mma16816(acc2[i * 2 + 1],     al0, wh[i][1], wh[i][3]);
        }
        #pragma unroll
        for (int i = 0; i < 4; ++i) {
            mma16816(acc2[8 + i * 2],     al1, wh[i][0], wh[i][2]);
            mma16816(acc2[8 + i * 2 + 1], al1, wh[i][1], wh[i][3]);
        }
    }

    // ---------------- epilogue (warp-uniform branch, coalesced [t][ch]) ------
    if (wn == 0) {                         // out-ch 0..63 -> skip
        #pragma unroll
        for (int mf = 0; mf < 2; ++mf) {
            const int trowA = t0 + mbase + mf * 16 + r;
            const int trowB = trowA + 8;
            #pragma unroll
            for (int i = 0; i < 4; ++i) {
                #pragma unroll
                for (int p = 0; p < 2; ++p) {
                    const int ch = i * 16 + p * 8 + 2 * q;
                    const float* d = acc2[(mf * 4 + i) * 2 + p];
                    float bs0 = sbd[128 + ch], bs1 = sbd[128 + ch + 1];
                    float2* p1 = (float2*)&skip[((size_t)b * TLEN + trowA) * 64 + ch];
                    float2* p2 = (float2*)&skip[((size_t)b * TLEN + trowB) * 64 + ch];
                    float2 v1 = *p1, v2 = *p2;
                    v1.x += d[0] + bs0; v1.y += d[1] + bs1;
                    v2.x += d[2] + bs0; v2.y += d[3] + bs1;
                    *p1 = v1; *p2 = v2;
                }
            }
        }
    } else {                               // out-ch 64..127 -> residual
        #pragma unroll
        for (int mf = 0; mf < 2; ++mf) {
            const int trowA = t0 + mbase + mf * 16 + r;
            const int trowB = trowA + 8;
            #pragma unroll
            for (int i = 0; i < 4; ++i) {
                #pragma unroll
                for (int p = 0; p < 2; ++p) {
                    const int ch = i * 16 + p * 8 + 2 * q;
                    const float* d = acc2[(mf * 4 + i) * 2 + p];
                    float br0 = sbd[192 + ch], br1 = sbd[192 + ch + 1];
                    size_t e1 = ((size_t)b * TLEN + trowA) * 64 + ch;
                    size_t e2 = ((size_t)b * TLEN + trowB) * 64 + ch;
                    __nv_bfloat162 iH1 = *(__nv_bfloat162*)&hinH[e1];
                    __nv_bfloat162 iL1 = *(__nv_bfloat162*)&hinL[e1];
                    __nv_bfloat162 iH2 = *(__nv_bfloat162*)&hinH[e2];
                    __nv_bfloat162 iL2 = *(__nv_bfloat162*)&hinL[e2];
                    float h10 = (d[0] + br0 + __bfloat162float(iH1.x) + __bfloat162float(iL1.x)) * SQRT_HALF;
                    float h11 = (d[1] + br1 + __bfloat162float(iH1.y) + __bfloat162float(iL1.y)) * SQRT_HALF;
                    float h20 = (d[2] + br0 + __bfloat162float(iH2.x) + __bfloat162float(iL2.x)) * SQRT_HALF;
                    float h21 = (d[3] + br1 + __bfloat162float(iH2.y) + __bfloat162float(iL2.y)) * SQRT_HALF;
                    uint32_t oh1 = packbf2(h10, h11);
                    uint32_t oh2 = packbf2(h20, h21);
                    __nv_bfloat162 hh1 = *(__nv_bfloat162*)&oh1;
                    __nv_bfloat162 hh2 = *(__nv_bfloat162*)&oh2;
                    uint32_t ol1 = packbf2(h10 - __bfloat162float(hh1.x), h11 - __bfloat162float(hh1.y));
                    uint32_t ol2 = packbf2(h20 - __bfloat162float(hh2.x), h21 - __bfloat162float(hh2.y));
                    *(uint32_t*)&houtH[e1] = oh1;
                    *(uint32_t*)&houtL[e1] = ol1;
                    *(uint32_t*)&houtH[e2] = oh2;
                    *(uint32_t*)&houtL[e2] = ol2;
                }
            }
        }
    }
}

// ======================= final head ==========================================
__global__ void final2(const float* __restrict__ skip,
                       const float* __restrict__ Wl1, const float* __restrict__ bl1,
                       const float* __restrict__ Wl2, const float* __restrict__ bl2,
                       float* __restrict__ out) {
    __shared__ float tile[128 * 65];
    __shared__ float b1s[64];
    __shared__ float W2s[64];
    int tid = threadIdx.x;   // 128
    if (tid < 64) { b1s[tid] = bl1[tid]; W2s[tid] = Wl2[tid]; }
    int t0 = (blockIdx.x & 255) * 128;
    int b  = blockIdx.x >> 8;
    for (int i = tid; i < 128 * 64; i += 128) {
        int rr = i >> 6, cc = i & 63;
        tile[rr * 65 + cc] = skip[((size_t)b * TLEN + t0) * 64 + i];
    }
    __syncthreads();
    float s1[64];
    #pragma unroll 8
    for (int j = 0; j < 64; ++j)
        s1[j] = fmaxf(tile[tid * 65 + j] * SQRT_INV_L, 0.f);
    float y2 = bl2[0];
    for (int o = 0; o < 64; ++o) {
        float a = b1s[o];
        #pragma unroll 8
        for (int j = 0; j < 64; ++j) a += Wl1[o * 64 + j] * s1[j];
        y2 += W2s[o] * fmaxf(a, 0.f);
    }
    out[(size_t)b * TLEN + t0 + tid] = y2;
}

// ======================= launch ==============================================
extern "C" void kernel_launch(void* const* d_in, const int* in_sizes, int n_in,
                              void* d_out, int out_size)
{
    const float* x       = (const float*)d_in[0];
    const float* c       = (const float*)d_in[1];
    const float* W_first = (const float*)d_in[2];
    const float* b_first = (const float*)d_in[3];
    const float* W_cin   = (const float*)d_in[4];
    const float* W_up    = (const float*)d_in[5];
    const float* Wd      = (const float*)d_in[6];
    const float* bd      = (const float*)d_in[7];
    const float* Wa      = (const float*)d_in[8];
    const float* Ws      = (const float*)d_in[9];
    const float* bs      = (const float*)d_in[10];
    const float* Wr      = (const float*)d_in[11];
    const float* br      = (const float*)d_in[12];
    const float* Wl1     = (const float*)d_in[13];
    const float* bl1     = (const float*)d_in[14];
    const float* Wl2     = (const float*)d_in[15];
    const float* bl2     = (const float*)d_in[16];
    float* out = (float*)d_out;

    float *skip;
    __nv_bfloat16 *hHa, *hLa, *hHb, *hLb, *cPH, *cPL, *WgH, *WgL, *W2H, *W2L;
    cudaGetSymbolAddress((void**)&skip, g_skip);
    cudaGetSymbolAddress((void**)&hHa,  g_hHa);
    cudaGetSymbolAddress((void**)&hLa,  g_hLa);
    cudaGetSymbolAddress((void**)&hHb,  g_hHb);
    cudaGetSymbolAddress((void**)&hLb,  g_hLb);
    cudaGetSymbolAddress((void**)&cPH,  g_cPH);
    cudaGetSymbolAddress((void**)&cPL,  g_cPL);
    cudaGetSymbolAddress((void**)&WgH,  g_WgH);
    cudaGetSymbolAddress((void**)&WgL,  g_WgL);
    cudaGetSymbolAddress((void**)&W2H,  g_W2H);
    cudaGetSymbolAddress((void**)&W2L,  g_W2L);

    const int COND_SMEM = (80 * 6 + 80 * 8 + 80 * 8 + 80 * 14 + 80 * 36 + 80 * 128) * 4;
    cudaFuncSetAttribute(cond_fused, cudaFuncAttributeMaxDynamicSharedMemorySize, COND_SMEM);
    cudaFuncSetAttribute(layer_mma, cudaFuncAttributeMaxDynamicSharedMemorySize, SMEM_NEED);

    {
        dim3 grid(TLEN / 128, NB);
        cond_fused<<<grid, 256, COND_SMEM>>>(c, W_cin, W_up, cPH, cPL);
    }
    {
        int N = NLAYERS * 5 * 128 * 64 + NLAYERS * 128 * 64;
        prepack_w<<<(N + 255) / 256, 256>>>(Wd, Wa, Ws, Wr, WgH, WgL, W2H, W2L);
    }
    {
        int N = NB * TLEN * RC;
        first_pack<<<(N + 255) / 256, 256>>>(x, W_first, b_first, hHa, hLa, skip);
    }
    __nv_bfloat16 *hiH = hHa, *hiL = hLa, *hoH = hHb, *hoL = hLb;
    dim3 grid(TLEN / 128, NB);
    for (int i = 0; i < NLAYERS; ++i) {
        int d = 1 << (i % 10);
        layer_mma<<<grid, 256, SMEM_NEED>>>(i, d, hiH, hiL, hoH, hoL,
                                            cPH, cPL, skip, WgH, WgL, W2H, W2L, bd, bs, br);
        { __nv_bfloat16* t = hiH; hiH = hoH; hoH = t; }
        { __nv_bfloat16* t = hiL; hiL = hoL; hoL = t; }
    }
    final2<<<NB * (TLEN / 128), 128>>>(skip, Wl1, bl1, Wl2, bl2, out);
}

// round 9
// speedup vs baseline: 1.7552x; 1.7512x over previous
#include <cuda_runtime.h>
#include <cuda_fp16.h>
#include <math.h>
#include <stdint.h>

#define TLEN 32768
#define NB 2
#define RC 64
#define GC 128
#define SC 64
#define AC 80
#define NLAYERS 30
#define SQRT_HALF 0.70710678118654752440f
#define SQRT_INV_L 0.18257418583505537115f

// ======================= scratch (device globals) ============================
__device__ float g_h32a[NB * TLEN * RC];                    // fp32 residual carry
__device__ float g_h32b[NB * TLEN * RC];
__device__ __align__(16) __half g_h16a[NB * TLEN * RC];     // fp16 MMA snapshot
__device__ __align__(16) __half g_h16b[NB * TLEN * RC];
__device__ float g_skip[NB * TLEN * SC];
__device__ __align__(16) __half g_c16[NB * 2 * TLEN * 64];
__device__ __align__(16) __half g_Wg16[NLAYERS * 5 * 128 * 64];
__device__ __align__(16) __half g_W216[NLAYERS * 128 * 64];

// ======================= helpers =============================================
__device__ __forceinline__ uint32_t smem_u32(const void* p) {
    uint32_t a;
    asm("{ .reg .u64 t; cvta.to.shared.u64 t, %1; cvt.u32.u64 %0, t; }" : "=r"(a) : "l"(p));
    return a;
}
__device__ __forceinline__ void ldm4(uint32_t* r, uint32_t addr) {
    asm volatile("ldmatrix.sync.aligned.m8n8.x4.shared.b16 {%0,%1,%2,%3}, [%4];"
        : "=r"(r[0]), "=r"(r[1]), "=r"(r[2]), "=r"(r[3]) : "r"(addr));
}
__device__ __forceinline__ void mma16816(float* d, const uint32_t* a, uint32_t b0, uint32_t b1) {
    asm volatile("mma.sync.aligned.m16n8k16.row.col.f32.f16.f16.f32 "
        "{%0,%1,%2,%3}, {%4,%5,%6,%7}, {%8,%9}, {%0,%1,%2,%3};"
        : "+f"(d[0]), "+f"(d[1]), "+f"(d[2]), "+f"(d[3])
        : "r"(a[0]), "r"(a[1]), "r"(a[2]), "r"(a[3]), "r"(b0), "r"(b1));
}
__device__ __forceinline__ void cpa16(uint32_t dst, const void* src, int srcsz) {
    asm volatile("cp.async.ca.shared.global [%0], [%1], 16, %2;"
        :: "r"(dst), "l"(src), "r"(srcsz) : "memory");
}
#define CP_COMMIT() asm volatile("cp.async.commit_group;" ::: "memory")
#define CP_WAIT0()  asm volatile("cp.async.wait_group 0;" ::: "memory")

__device__ __forceinline__ uint32_t packh2(float lo, float hi) {
    __half2 t = __floats2half2_rn(lo, hi);
    return *(uint32_t*)&t;
}

// ======================= fused conditioning ==================================
__global__ void cond_fused(const float* __restrict__ c, const float* __restrict__ Wc,
                           const float* __restrict__ Wup,
                           __half* __restrict__ P16) {
    extern __shared__ float us[];
    const int b  = blockIdx.y;
    const int t0 = blockIdx.x * 128;
    const int tid = threadIdx.x;   // 256

    const int u0 = (t0 - 4) >> 2;
    const int un = ((t0 + 131) >> 2) - u0 + 1;
    const int v0 = (u0 - 4) >> 2;
    const int vn = ((u0 + un - 1 + 4) >> 2) - v0 + 1;
    const int w0 = (v0 - 4) >> 2;
    const int wn = ((v0 + vn - 1 + 4) >> 2) - w0 + 1;
    const int f0 = (w0 - 4) >> 2;
    const int fn = ((w0 + wn - 1 + 4) >> 2) - f0 + 1;

    float* y0 = us;
    float* y1 = y0 + 80 * 6;
    float* s1 = y1 + 80 * 8;
    float* s2 = s1 + 80 * 8;
    float* s3 = s2 + 80 * 14;
    float* s4 = s3 + 80 * 36;

    for (int i = tid; i < 80 * fn; i += 256) {
        int ch = i / fn, ff = i - ch * fn;
        int f = f0 + ff;
        y0[ch * 6 + ff] = (f >= 0 && f < 128) ? c[((size_t)b * 80 + ch) * 128 + f] : 0.f;
    }
    __syncthreads();
    for (int i = tid; i < 80 * fn; i += 256) {
        int o = i / fn, ff = i - o * fn;
        float acc = 0.f;
        #pragma unroll 4
        for (int k = 0; k < 80; ++k) acc += Wc[o * 80 + k] * y0[k * 6 + ff];
        y1[o * 8 + ff] = acc;
    }
    __syncthreads();
    for (int i = tid; i < 80 * wn; i += 256) {
        int o = i / wn, wi = i - o * wn;
        int w = w0 + wi;
        float acc = 0.f;
        #pragma unroll
        for (int k = 0; k < 9; ++k) {
            int rr = w - 4 + k;
            if (rr >= 0 && rr < 512) acc += Wup[k] * y1[o * 8 + ((rr >> 2) - f0)];
        }
        s1[o * 8 + wi] = acc;
    }
    __syncthreads();
    for (int i = tid; i < 80 * vn; i += 256) {
        int o = i / vn, vi = i - o * vn;
        int v = v0 + vi;
        float acc = 0.f;
        #pragma unroll
        for (int k = 0; k < 9; ++k) {
            int rr = v - 4 + k;
            if (rr >= 0 && rr < 2048) acc += Wup[9 + k] * s1[o * 8 + ((rr >> 2) - w0)];
        }
        s2[o * 14 + vi] = acc;
    }
    __syncthreads();
    for (int i = tid; i < 80 * un; i += 256) {
        int o = i / un, ui = i - o * un;
        int u = u0 + ui;
        float acc = 0.f;
        #pragma unroll
        for (int k = 0; k < 9; ++k) {
            int rr = u - 4 + k;
            if (rr >= 0 && rr < 8192) acc += Wup[18 + k] * s2[o * 14 + ((rr >> 2) - v0)];
        }
        s3[o * 36 + ui] = acc;
    }
    __syncthreads();
    for (int i = tid; i < 80 * 128; i += 256) {
        int o = i >> 7, tl = i & 127;
        int t = t0 + tl;
        float acc = 0.f;
        #pragma unroll
        for (int k = 0; k < 9; ++k) {
            int rr = t - 4 + k;
            if (rr >= 0 && rr < TLEN) acc += Wup[27 + k] * s3[o * 36 + ((rr >> 2) - u0)];
        }
        s4[o * 128 + tl] = acc;
    }
    __syncthreads();
    for (int i = tid; i < 128 * 64; i += 256) {
        int tl = i >> 6, j = i & 63;
        size_t o0 = (((size_t)b * 2 + 0) * TLEN + (t0 + tl)) * 64 + j;
        size_t o1 = (((size_t)b * 2 + 1) * TLEN + (t0 + tl)) * 64 + j;
        float v0f = s4[j * 128 + tl];
        float v1f = (j < 16) ? s4[(64 + j) * 128 + tl] : 0.f;
        P16[o0] = __float2half(v0f);
        P16[o1] = __float2half(v1f);
    }
}

// ======================= weight prepack ======================================
__global__ void prepack_w(const float* __restrict__ Wd, const float* __restrict__ Wa,
                          const float* __restrict__ Ws, const float* __restrict__ Wr,
                          __half* __restrict__ Wg16, __half* __restrict__ W216) {
    const int N1 = NLAYERS * 5 * 128 * 64;
    const int N2 = NLAYERS * 128 * 64;
    int i = blockIdx.x * blockDim.x + threadIdx.x;
    if (i < N1) {
        int kl = i & 63;
        int r  = (i >> 6) & 127;
        int lc = i >> 13;
        int cc = lc % 5;
        int l  = lc / 5;
        int j  = ((r >> 4) << 3) + (((r & 7) >> 1) << 1) + ((r >> 3) & 1);
        int ch = (r & 1) ? (64 + j) : j;
        float w;
        if (cc < 3)       w = Wd[(((size_t)l * GC + ch) * RC + kl) * 3 + cc];
        else if (cc == 3) w = Wa[((size_t)l * GC + ch) * AC + kl];
        else              w = (kl < AC - 64) ? Wa[((size_t)l * GC + ch) * AC + 64 + kl] : 0.f;
        Wg16[i] = __float2half(w);
    } else if (i - N1 < N2) {
        int i2 = i - N1;
        int k  = i2 & 63;
        int r2 = (i2 >> 6) & 127;
        int l  = i2 >> 13;
        float w = (r2 < 64) ? Ws[((size_t)l * SC + r2) * 64 + k]
                            : Wr[((size_t)l * RC + (r2 - 64)) * 64 + k];
        W216[i2] = __float2half(w);
    }
}

__global__ void first_pack(const float* __restrict__ x,
                           const float* __restrict__ Wf, const float* __restrict__ bf,
                           float* __restrict__ h32, __half* __restrict__ h16,
                           float* __restrict__ skip) {
    int idx = blockIdx.x * blockDim.x + threadIdx.x;
    if (idx >= NB * TLEN * RC) return;
    int j = idx & 63;
    int t = (idx >> 6) & (TLEN - 1);
    int b = idx >> 21;
    float v = Wf[j] * x[(size_t)b * TLEN + t] + bf[j];
    h32[idx] = v;
    h16[idx] = __float2half(v);
    skip[idx] = 0.f;
}

// ======================= fused residual layer ================================
// smem: 2 regions of 128 rows x 144B (64 fp16 + pad). W = weights; D = data/z.
#define STRIDE 144
#define OFF_WH  0
#define OFF_DH  (128 * STRIDE)
#define OFF_BD  (2 * 128 * STRIDE)
#define SMEM_NEED (OFF_BD + 1024)

__global__ __launch_bounds__(256, 2)
void layer_mma(int l, int dil,
               const float* __restrict__ hin32, float* __restrict__ hout32,
               const __half* __restrict__ hin16, __half* __restrict__ hout16,
               const __half* __restrict__ c16,
               float* __restrict__ skip,
               const __half* __restrict__ Wg16, const __half* __restrict__ W216,
               const float* __restrict__ bd, const float* __restrict__ bs,
               const float* __restrict__ br) {
    extern __shared__ char smem_c[];
    const uint32_t sb = smem_u32(smem_c);
    float* sbd = (float*)(smem_c + OFF_BD);

    const int tid  = threadIdx.x;
    const int warp = tid >> 5;
    const int lane = tid & 31;
    const int b    = blockIdx.y;
    const int t0   = blockIdx.x * 128;

    const int wm    = warp & 3;       // t-tile (32 rows)
    const int wn    = warp >> 2;      // n-tile (64 cols)
    const int mbase = wm * 32;
    const int nbase = wn * 64;

    const int lrow  = lane & 15;
    const int lkoff = (lane >> 4) * 16;
    const int q     = lane & 3;
    const int r     = lane >> 2;

    // biases: bd[0..127], bs[128..191], br[192..255]
    if (tid < 128)      sbd[tid] = bd[l * GC + tid];
    else if (tid < 192) sbd[tid] = bs[l * SC + tid - 128];
    else                sbd[tid] = br[l * RC + tid - 192];

    // ---- chunk staging via cp.async ----
    auto stage_chunk = [&](int c) {
        const char* wb = (const char*)(Wg16 + (((size_t)l * 5 + c) * 128) * 64);
        #pragma unroll
        for (int it = 0; it < 4; ++it) {
            const int p = it * 256 + tid;
            const int row = p >> 3, j = p & 7;
            if (c == 4 && j >= 2) continue;
            const uint32_t d = (uint32_t)row * STRIDE + j * 16;
            cpa16(sb + OFF_WH + d, wb + p * 16, 16);
            const char* src; int sz = 16;
            if (c < 3) {
                int tg = t0 + row + (c - 1) * dil;
                if (tg >= 0 && tg < TLEN) {
                    src = (const char*)hin16 + ((size_t)b * TLEN + tg) * 128 + j * 16;
                } else { src = (const char*)hin16; sz = 0; }
            } else {
                src = (const char*)c16
                    + (((size_t)b * 2 + (c - 3)) * TLEN + (t0 + row)) * 128 + j * 16;
            }
            cpa16(sb + OFF_DH + d, src, sz);
        }
        CP_COMMIT();
    };

    stage_chunk(0);

    float acc[16][4];
    #pragma unroll
    for (int i = 0; i < 16; ++i)
        #pragma unroll
        for (int j2 = 0; j2 < 4; ++j2) acc[i][j2] = 0.f;

    // ---------------- GEMM1: D1[t 32][gch 64] per warp ----------------
    for (int c = 0; c < 5; ++c) {
        CP_WAIT0();
        __syncthreads();
        const int nks = (c == 4) ? 1 : 4;
        for (int ks = 0; ks < nks; ++ks) {
            uint32_t a0f[4], a1f[4];
            const uint32_t a0 = sb + OFF_DH + (uint32_t)(mbase + lrow) * STRIDE + lkoff + ks * 32;
            ldm4(a0f, a0);
            ldm4(a1f, a0 + 16 * STRIDE);
            uint32_t bf4[4][4];
            #pragma unroll
            for (int i = 0; i < 4; ++i) {
                uint32_t baddr = sb + OFF_WH + (uint32_t)(nbase + i * 16 + lrow) * STRIDE + lkoff + ks * 32;
                ldm4(bf4[i], baddr);
            }
            #pragma unroll
            for (int i = 0; i < 4; ++i) {
                mma16816(acc[i * 2],         a0f, bf4[i][0], bf4[i][2]);
                mma16816(acc[i * 2 + 1],     a0f, bf4[i][1], bf4[i][3]);
            }
            #pragma unroll
            for (int i = 0; i < 4; ++i) {
                mma16816(acc[8 + i * 2],     a1f, bf4[i][0], bf4[i][2]);
                mma16816(acc[8 + i * 2 + 1], a1f, bf4[i][1], bf4[i][3]);
            }
        }
        __syncthreads();
        if (c < 4) stage_chunk(c + 1);
    }

    // stage W2 into W region (overlaps gate)
    {
        const char* wb = (const char*)(W216 + (size_t)l * 128 * 64);
        #pragma unroll
        for (int it = 0; it < 4; ++it) {
            const int p = it * 256 + tid;
            const int row = p >> 3, j = p & 7;
            cpa16(sb + OFF_WH + (uint32_t)row * STRIDE + j * 16, wb + p * 16, 16);
        }
        CP_COMMIT();
    }

    // ---------------- gate -> z into D region (fp16) -------------------------
    #pragma unroll
    for (int mf = 0; mf < 2; ++mf) {
        const int tr0 = mbase + mf * 16 + r;
        #pragma unroll
        for (int i = 0; i < 4; ++i) {
            #pragma unroll
            for (int p = 0; p < 2; ++p) {
                const int j = (wn * 4 + i) * 8 + 2 * q + p;
                const float ba = sbd[j], bb = sbd[64 + j];
                const float* a = acc[(mf * 4 + i) * 2 + p];
                #pragma unroll
                for (int h = 0; h < 2; ++h) {
                    float xa = a[h * 2 + 0] + ba;
                    float xb = a[h * 2 + 1] + bb;
                    float e2 = __expf(-2.f * fabsf(xa));
                    float th = copysignf(__fdividef(1.f - e2, 1.f + e2), xa);
                    float sg = __fdividef(1.f, 1.f + __expf(-xb));
                    float z  = th * sg;
                    const int tr = tr0 + h * 8;
                    *(__half*)(smem_c + OFF_DH + (uint32_t)tr * STRIDE + j * 2) = __float2half(z);
                }
            }
        }
    }

    CP_WAIT0();
    __syncthreads();

    // ---------------- GEMM2: D2[t 32][och 64] = z * W2^T ----------------
    float acc2[16][4];
    #pragma unroll
    for (int i = 0; i < 16; ++i)
        #pragma unroll
        for (int j2 = 0; j2 < 4; ++j2) acc2[i][j2] = 0.f;

    #pragma unroll
    for (int ks = 0; ks < 4; ++ks) {
        uint32_t a0f[4], a1f[4];
        const uint32_t a0 = sb + OFF_DH + (uint32_t)(mbase + lrow) * STRIDE + lkoff + ks * 32;
        ldm4(a0f, a0);
        ldm4(a1f, a0 + 16 * STRIDE);
        uint32_t wf4[4][4];
        #pragma unroll
        for (int i = 0; i < 4; ++i) {
            uint32_t baddr = sb + OFF_WH + (uint32_t)(nbase + i * 16 + lrow) * STRIDE + lkoff + ks * 32;
            ldm4(wf4[i], baddr);
        }
        #pragma unroll
        for (int i = 0; i < 4; ++i) {
            mma16816(acc2[i * 2],         a0f, wf4[i][0], wf4[i][2]);
            mma16816(acc2[i * 2 + 1],     a0f, wf4[i][1], wf4[i][3]);
        }
        #pragma unroll
        for (int i = 0; i < 4; ++i) {
            mma16816(acc2[8 + i * 2],     a1f, wf4[i][0], wf4[i][2]);
            mma16816(acc2[8 + i * 2 + 1], a1f, wf4[i][1], wf4[i][3]);
        }
    }

    // ---------------- epilogue (warp-uniform, coalesced [t][ch]) -------------
    if (wn == 0) {                         // out-ch 0..63 -> skip
        #pragma unroll
        for (int mf = 0; mf < 2; ++mf) {
            const int trowA = t0 + mbase + mf * 16 + r;
            const int trowB = trowA + 8;
            #pragma unroll
            for (int i = 0; i < 4; ++i) {
                #pragma unroll
                for (int p = 0; p < 2; ++p) {
                    const int ch = i * 16 + p * 8 + 2 * q;
                    const float* d = acc2[(mf * 4 + i) * 2 + p];
                    float bs0 = sbd[128 + ch], bs1 = sbd[128 + ch + 1];
                    float2* p1 = (float2*)&skip[((size_t)b * TLEN + trowA) * 64 + ch];
                    float2* p2 = (float2*)&skip[((size_t)b * TLEN + trowB) * 64 + ch];
                    float2 v1 = *p1, v2 = *p2;
                    v1.x += d[0] + bs0; v1.y += d[1] + bs1;
                    v2.x += d[2] + bs0; v2.y += d[3] + bs1;
                    *p1 = v1; *p2 = v2;
                }
            }
        }
    } else {                               // out-ch 64..127 -> residual
        #pragma unroll
        for (int mf = 0; mf < 2; ++mf) {
            const int trowA = t0 + mbase + mf * 16 + r;
            const int trowB = trowA + 8;
            #pragma unroll
            for (int i = 0; i < 4; ++i) {
                #pragma unroll
                for (int p = 0; p < 2; ++p) {
                    const int ch = i * 16 + p * 8 + 2 * q;
                    const float* d = acc2[(mf * 4 + i) * 2 + p];
                    float br0 = sbd[192 + ch], br1 = sbd[192 + ch + 1];
                    size_t e1 = ((size_t)b * TLEN + trowA) * 64 + ch;
                    size_t e2 = ((size_t)b * TLEN + trowB) * 64 + ch;
                    float2 i1 = *(const float2*)&hin32[e1];
                    float2 i2 = *(const float2*)&hin32[e2];
                    float h10 = (d[0] + br0 + i1.x) * SQRT_HALF;
                    float h11 = (d[1] + br1 + i1.y) * SQRT_HALF;
                    float h20 = (d[2] + br0 + i2.x) * SQRT_HALF;
                    float h21 = (d[3] + br1 + i2.y) * SQRT_HALF;
                    *(float2*)&hout32[e1] = make_float2(h10, h11);
                    *(float2*)&hout32[e2] = make_float2(h20, h21);
                    *(uint32_t*)&hout16[e1] = packh2(h10, h11);
                    *(uint32_t*)&hout16[e2] = packh2(h20, h21);
                }
            }
        }
    }
}

// ======================= final head ==========================================
__global__ void final2(const float* __restrict__ skip,
                       const float* __restrict__ Wl1, const float* __restrict__ bl1,
                       const float* __restrict__ Wl2, const float* __restrict__ bl2,
                       float* __restrict__ out) {
    __shared__ float tile[128 * 65];
    __shared__ float b1s[64];
    __shared__ float W2s[64];
    int tid = threadIdx.x;   // 128
    if (tid < 64) { b1s[tid] = bl1[tid]; W2s[tid] = Wl2[tid]; }
    int t0 = (blockIdx.x & 255) * 128;
    int b  = blockIdx.x >> 8;
    for (int i = tid; i < 128 * 64; i += 128) {
        int rr = i >> 6, cc = i & 63;
        tile[rr * 65 + cc] = skip[((size_t)b * TLEN + t0) * 64 + i];
    }
    __syncthreads();
    float s1[64];
    #pragma unroll 8
    for (int j = 0; j < 64; ++j)
        s1[j] = fmaxf(tile[tid * 65 + j] * SQRT_INV_L, 0.f);
    float y2 = bl2[0];
    for (int o = 0; o < 64; ++o) {
        float a = b1s[o];
        #pragma unroll 8
        for (int j = 0; j < 64; ++j) a += Wl1[o * 64 + j] * s1[j];
        y2 += W2s[o] * fmaxf(a, 0.f);
    }
    out[(size_t)b * TLEN + t0 + tid] = y2;
}

// ======================= launch ==============================================
extern "C" void kernel_launch(void* const* d_in, const int* in_sizes, int n_in,
                              void* d_out, int out_size)
{
    const float* x       = (const float*)d_in[0];
    const float* c       = (const float*)d_in[1];
    const float* W_first = (const float*)d_in[2];
    const float* b_first = (const float*)d_in[3];
    const float* W_cin   = (const float*)d_in[4];
    const float* W_up    = (const float*)d_in[5];
    const float* Wd      = (const float*)d_in[6];
    const float* bd      = (const float*)d_in[7];
    const float* Wa      = (const float*)d_in[8];
    const float* Ws      = (const float*)d_in[9];
    const float* bs      = (const float*)d_in[10];
    const float* Wr      = (const float*)d_in[11];
    const float* br      = (const float*)d_in[12];
    const float* Wl1     = (const float*)d_in[13];
    const float* bl1     = (const float*)d_in[14];
    const float* Wl2     = (const float*)d_in[15];
    const float* bl2     = (const float*)d_in[16];
    float* out = (float*)d_out;

    float *skip, *h32a, *h32b;
    __half *h16a, *h16b, *c16, *Wg16, *W216;
    cudaGetSymbolAddress((void**)&skip, g_skip);
    cudaGetSymbolAddress((void**)&h32a, g_h32a);
    cudaGetSymbolAddress((void**)&h32b, g_h32b);
    cudaGetSymbolAddress((void**)&h16a, g_h16a);
    cudaGetSymbolAddress((void**)&h16b, g_h16b);
    cudaGetSymbolAddress((void**)&c16,  g_c16);
    cudaGetSymbolAddress((void**)&Wg16, g_Wg16);
    cudaGetSymbolAddress((void**)&W216, g_W216);

    const int COND_SMEM = (80 * 6 + 80 * 8 + 80 * 8 + 80 * 14 + 80 * 36 + 80 * 128) * 4;
    cudaFuncSetAttribute(cond_fused, cudaFuncAttributeMaxDynamicSharedMemorySize, COND_SMEM);
    cudaFuncSetAttribute(layer_mma, cudaFuncAttributeMaxDynamicSharedMemorySize, SMEM_NEED);

    {
        dim3 grid(TLEN / 128, NB);
        cond_fused<<<grid, 256, COND_SMEM>>>(c, W_cin, W_up, c16);
    }
    {
        int N = NLAYERS * 5 * 128 * 64 + NLAYERS * 128 * 64;
        prepack_w<<<(N + 255) / 256, 256>>>(Wd, Wa, Ws, Wr, Wg16, W216);
    }
    {
        int N = NB * TLEN * RC;
        first_pack<<<(N + 255) / 256, 256>>>(x, W_first, b_first, h32a, h16a, skip);
    }
    float *hi32 = h32a, *ho32 = h32b;
    __half *hi16 = h16a, *ho16 = h16b;
    dim3 grid(TLEN / 128, NB);
    for (int i = 0; i < NLAYERS; ++i) {
        int d = 1 << (i % 10);
        layer_mma<<<grid, 256, SMEM_NEED>>>(i, d, hi32, ho32, hi16, ho16,
                                            c16, skip, Wg16, W216, bd, bs, br);
        { float* t = hi32; hi32 = ho32; ho32 = t; }
        { __half* t = hi16; hi16 = ho16; ho16 = t; }
    }
    final2<<<NB * (TLEN / 128), 128>>>(skip, Wl1, bl1, Wl2, bl2, out);
}

// round 10
// speedup vs baseline: 1.7819x; 1.0152x over previous
#include <cuda_runtime.h>
#include <cuda_fp16.h>
#include <math.h>
#include <stdint.h>

#define TLEN 32768
#define NB 2
#define RC 64
#define GC 128
#define SC 64
#define AC 80
#define NLAYERS 30
#define SQRT_HALF 0.70710678118654752440f
#define SQRT_INV_L 0.18257418583505537115f

// ======================= scratch (device globals) ============================
__device__ float g_h32a[NB * TLEN * RC];                    // fp32 residual carry
__device__ float g_h32b[NB * TLEN * RC];
__device__ __align__(16) __half g_h16a[NB * TLEN * RC];     // fp16 MMA snapshot
__device__ __align__(16) __half g_h16b[NB * TLEN * RC];
__device__ float g_skip[NB * TLEN * SC];
__device__ __align__(16) __half g_c16[NB * 2 * TLEN * 64];
__device__ __align__(16) __half g_Wg16[NLAYERS * 5 * 128 * 64];
__device__ __align__(16) __half g_W216[NLAYERS * 128 * 64];

// ======================= helpers =============================================
__device__ __forceinline__ uint32_t smem_u32(const void* p) {
    uint32_t a;
    asm("{ .reg .u64 t; cvta.to.shared.u64 t, %1; cvt.u32.u64 %0, t; }" : "=r"(a) : "l"(p));
    return a;
}
__device__ __forceinline__ void ldm4(uint32_t* r, uint32_t addr) {
    asm volatile("ldmatrix.sync.aligned.m8n8.x4.shared.b16 {%0,%1,%2,%3}, [%4];"
        : "=r"(r[0]), "=r"(r[1]), "=r"(r[2]), "=r"(r[3]) : "r"(addr));
}
__device__ __forceinline__ void mma16816(float* d, const uint32_t* a, uint32_t b0, uint32_t b1) {
    asm volatile("mma.sync.aligned.m16n8k16.row.col.f32.f16.f16.f32 "
        "{%0,%1,%2,%3}, {%4,%5,%6,%7}, {%8,%9}, {%0,%1,%2,%3};"
        : "+f"(d[0]), "+f"(d[1]), "+f"(d[2]), "+f"(d[3])
        : "r"(a[0]), "r"(a[1]), "r"(a[2]), "r"(a[3]), "r"(b0), "r"(b1));
}
__device__ __forceinline__ void cpa16(uint32_t dst, const void* src, int srcsz) {
    asm volatile("cp.async.ca.shared.global [%0], [%1], 16, %2;"
        :: "r"(dst), "l"(src), "r"(srcsz) : "memory");
}
#define CP_COMMIT() asm volatile("cp.async.commit_group;" ::: "memory")
#define CP_WAIT0()  asm volatile("cp.async.wait_group 0;" ::: "memory")
#define CP_WAIT1()  asm volatile("cp.async.wait_group 1;" ::: "memory")

__device__ __forceinline__ uint32_t packh2(float lo, float hi) {
    __half2 t = __floats2half2_rn(lo, hi);
    return *(uint32_t*)&t;
}

// ======================= fused conditioning ==================================
__global__ void cond_fused(const float* __restrict__ c, const float* __restrict__ Wc,
                           const float* __restrict__ Wup,
                           __half* __restrict__ P16) {
    extern __shared__ float us[];
    const int b  = blockIdx.y;
    const int t0 = blockIdx.x * 128;
    const int tid = threadIdx.x;   // 256

    const int u0 = (t0 - 4) >> 2;
    const int un = ((t0 + 131) >> 2) - u0 + 1;
    const int v0 = (u0 - 4) >> 2;
    const int vn = ((u0 + un - 1 + 4) >> 2) - v0 + 1;
    const int w0 = (v0 - 4) >> 2;
    const int wn = ((v0 + vn - 1 + 4) >> 2) - w0 + 1;
    const int f0 = (w0 - 4) >> 2;
    const int fn = ((w0 + wn - 1 + 4) >> 2) - f0 + 1;

    float* y0 = us;
    float* y1 = y0 + 80 * 6;
    float* s1 = y1 + 80 * 8;
    float* s2 = s1 + 80 * 8;
    float* s3 = s2 + 80 * 14;
    float* s4 = s3 + 80 * 36;

    for (int i = tid; i < 80 * fn; i += 256) {
        int ch = i / fn, ff = i - ch * fn;
        int f = f0 + ff;
        y0[ch * 6 + ff] = (f >= 0 && f < 128) ? c[((size_t)b * 80 + ch) * 128 + f] : 0.f;
    }
    __syncthreads();
    for (int i = tid; i < 80 * fn; i += 256) {
        int o = i / fn, ff = i - o * fn;
        float acc = 0.f;
        #pragma unroll 4
        for (int k = 0; k < 80; ++k) acc += Wc[o * 80 + k] * y0[k * 6 + ff];
        y1[o * 8 + ff] = acc;
    }
    __syncthreads();
    for (int i = tid; i < 80 * wn; i += 256) {
        int o = i / wn, wi = i - o * wn;
        int w = w0 + wi;
        float acc = 0.f;
        #pragma unroll
        for (int k = 0; k < 9; ++k) {
            int rr = w - 4 + k;
            if (rr >= 0 && rr < 512) acc += Wup[k] * y1[o * 8 + ((rr >> 2) - f0)];
        }
        s1[o * 8 + wi] = acc;
    }
    __syncthreads();
    for (int i = tid; i < 80 * vn; i += 256) {
        int o = i / vn, vi = i - o * vn;
        int v = v0 + vi;
        float acc = 0.f;
        #pragma unroll
        for (int k = 0; k < 9; ++k) {
            int rr = v - 4 + k;
            if (rr >= 0 && rr < 2048) acc += Wup[9 + k] * s1[o * 8 + ((rr >> 2) - w0)];
        }
        s2[o * 14 + vi] = acc;
    }
    __syncthreads();
    for (int i = tid; i < 80 * un; i += 256) {
        int o = i / un, ui = i - o * un;
        int u = u0 + ui;
        float acc = 0.f;
        #pragma unroll
        for (int k = 0; k < 9; ++k) {
            int rr = u - 4 + k;
            if (rr >= 0 && rr < 8192) acc += Wup[18 + k] * s2[o * 14 + ((rr >> 2) - v0)];
        }
        s3[o * 36 + ui] = acc;
    }
    __syncthreads();
    for (int i = tid; i < 80 * 128; i += 256) {
        int o = i >> 7, tl = i & 127;
        int t = t0 + tl;
        float acc = 0.f;
        #pragma unroll
        for (int k = 0; k < 9; ++k) {
            int rr = t - 4 + k;
            if (rr >= 0 && rr < TLEN) acc += Wup[27 + k] * s3[o * 36 + ((rr >> 2) - u0)];
        }
        s4[o * 128 + tl] = acc;
    }
    __syncthreads();
    for (int i = tid; i < 128 * 64; i += 256) {
        int tl = i >> 6, j = i & 63;
        size_t o0 = (((size_t)b * 2 + 0) * TLEN + (t0 + tl)) * 64 + j;
        size_t o1 = (((size_t)b * 2 + 1) * TLEN + (t0 + tl)) * 64 + j;
        float v0f = s4[j * 128 + tl];
        float v1f = (j < 16) ? s4[(64 + j) * 128 + tl] : 0.f;
        P16[o0] = __float2half(v0f);
        P16[o1] = __float2half(v1f);
    }
}

// ======================= weight prepack ======================================
__global__ void prepack_w(const float* __restrict__ Wd, const float* __restrict__ Wa,
                          const float* __restrict__ Ws, const float* __restrict__ Wr,
                          __half* __restrict__ Wg16, __half* __restrict__ W216) {
    const int N1 = NLAYERS * 5 * 128 * 64;
    const int N2 = NLAYERS * 128 * 64;
    int i = blockIdx.x * blockDim.x + threadIdx.x;
    if (i < N1) {
        int kl = i & 63;
        int r  = (i >> 6) & 127;
        int lc = i >> 13;
        int cc = lc % 5;
        int l  = lc / 5;
        int j  = ((r >> 4) << 3) + (((r & 7) >> 1) << 1) + ((r >> 3) & 1);
        int ch = (r & 1) ? (64 + j) : j;
        float w;
        if (cc < 3)       w = Wd[(((size_t)l * GC + ch) * RC + kl) * 3 + cc];
        else if (cc == 3) w = Wa[((size_t)l * GC + ch) * AC + kl];
        else              w = (kl < AC - 64) ? Wa[((size_t)l * GC + ch) * AC + 64 + kl] : 0.f;
        Wg16[i] = __float2half(w);
    } else if (i - N1 < N2) {
        int i2 = i - N1;
        int k  = i2 & 63;
        int r2 = (i2 >> 6) & 127;
        int l  = i2 >> 13;
        float w = (r2 < 64) ? Ws[((size_t)l * SC + r2) * 64 + k]
                            : Wr[((size_t)l * RC + (r2 - 64)) * 64 + k];
        W216[i2] = __float2half(w);
    }
}

__global__ void first_pack(const float* __restrict__ x,
                           const float* __restrict__ Wf, const float* __restrict__ bf,
                           float* __restrict__ h32, __half* __restrict__ h16,
                           float* __restrict__ skip) {
    int idx = blockIdx.x * blockDim.x + threadIdx.x;
    if (idx >= NB * TLEN * RC) return;
    int j = idx & 63;
    int t = (idx >> 6) & (TLEN - 1);
    int b = idx >> 21;
    float v = Wf[j] * x[(size_t)b * TLEN + t] + bf[j];
    h32[idx] = v;
    h16[idx] = __float2half(v);
    skip[idx] = 0.f;
}

// ======================= fused residual layer ================================
// double-buffered: W0,W1,D0,D1 regions of 128 rows x 144B; biases after.
#define STRIDE 144
#define RSZ (128 * STRIDE)
#define OFF_W0  0
#define OFF_D0  (2 * RSZ)
#define OFF_BD  (4 * RSZ)
#define SMEM_NEED (OFF_BD + 1024)

__global__ __launch_bounds__(256, 2)
void layer_mma(int l, int dil,
               const float* __restrict__ hin32, float* __restrict__ hout32,
               const __half* __restrict__ hin16, __half* __restrict__ hout16,
               const __half* __restrict__ c16,
               float* __restrict__ skip,
               const __half* __restrict__ Wg16, const __half* __restrict__ W216,
               const float* __restrict__ bd, const float* __restrict__ bs,
               const float* __restrict__ br) {
    extern __shared__ char smem_c[];
    const uint32_t sb = smem_u32(smem_c);
    float* sbd = (float*)(smem_c + OFF_BD);

    const int tid  = threadIdx.x;
    const int warp = tid >> 5;
    const int lane = tid & 31;
    const int b    = blockIdx.y;
    const int t0   = blockIdx.x * 128;

    const int wm    = warp & 3;       // t-tile (32 rows)
    const int wn    = warp >> 2;      // n-tile (64 cols)
    const int mbase = wm * 32;
    const int nbase = wn * 64;

    const int lrow  = lane & 15;
    const int lkoff = (lane >> 4) * 16;
    const int q     = lane & 3;
    const int r     = lane >> 2;

    // biases: bd[0..127], bs[128..191], br[192..255]
    if (tid < 128)      sbd[tid] = bd[l * GC + tid];
    else if (tid < 192) sbd[tid] = bs[l * SC + tid - 128];
    else                sbd[tid] = br[l * RC + tid - 192];

    // ---- chunk staging via cp.async (into buffer c&1) ----
    auto stage_chunk = [&](int c) {
        const int buf = c & 1;
        const char* wb = (const char*)(Wg16 + (((size_t)l * 5 + c) * 128) * 64);
        #pragma unroll
        for (int it = 0; it < 4; ++it) {
            const int p = it * 256 + tid;
            const int row = p >> 3, j = p & 7;
            if (c == 4 && j >= 2) continue;
            const uint32_t d = (uint32_t)row * STRIDE + j * 16;
            cpa16(sb + OFF_W0 + buf * RSZ + d, wb + p * 16, 16);
            const char* src; int sz = 16;
            if (c < 3) {
                int tg = t0 + row + (c - 1) * dil;
                if (tg >= 0 && tg < TLEN) {
                    src = (const char*)hin16 + ((size_t)b * TLEN + tg) * 128 + j * 16;
                } else { src = (const char*)hin16; sz = 0; }
            } else {
                src = (const char*)c16
                    + (((size_t)b * 2 + (c - 3)) * TLEN + (t0 + row)) * 128 + j * 16;
            }
            cpa16(sb + OFF_D0 + buf * RSZ + d, src, sz);
        }
        CP_COMMIT();
    };
    // W2 -> buf1 W region (after chunk 3 consumed)
    auto stage_w2 = [&]() {
        const char* wb = (const char*)(W216 + (size_t)l * 128 * 64);
        #pragma unroll
        for (int it = 0; it < 4; ++it) {
            const int p = it * 256 + tid;
            const int row = p >> 3, j = p & 7;
            cpa16(sb + OFF_W0 + RSZ + (uint32_t)row * STRIDE + j * 16, wb + p * 16, 16);
        }
        CP_COMMIT();
    };

    stage_chunk(0);
    stage_chunk(1);

    float acc[16][4];
    #pragma unroll
    for (int i = 0; i < 16; ++i)
        #pragma unroll
        for (int j2 = 0; j2 < 4; ++j2) acc[i][j2] = 0.f;

    // ---------------- GEMM1 pipeline: 5 chunks, double-buffered --------------
    for (int c = 0; c < 5; ++c) {
        CP_WAIT1();
        __syncthreads();
        const int buf = c & 1;
        const uint32_t dbase = sb + OFF_D0 + buf * RSZ;
        const uint32_t wbase = sb + OFF_W0 + buf * RSZ;
        const int nks = (c == 4) ? 1 : 4;
        for (int ks = 0; ks < nks; ++ks) {
            uint32_t a0f[4], a1f[4];
            const uint32_t a0 = dbase + (uint32_t)(mbase + lrow) * STRIDE + lkoff + ks * 32;
            ldm4(a0f, a0);
            ldm4(a1f, a0 + 16 * STRIDE);
            uint32_t bf4[4][4];
            #pragma unroll
            for (int i = 0; i < 4; ++i) {
                uint32_t baddr = wbase + (uint32_t)(nbase + i * 16 + lrow) * STRIDE + lkoff + ks * 32;
                ldm4(bf4[i], baddr);
            }
            #pragma unroll
            for (int i = 0; i < 4; ++i) {
                mma16816(acc[i * 2],         a0f, bf4[i][0], bf4[i][2]);
                mma16816(acc[i * 2 + 1],     a0f, bf4[i][1], bf4[i][3]);
            }
            #pragma unroll
            for (int i = 0; i < 4; ++i) {
                mma16816(acc[8 + i * 2],     a1f, bf4[i][0], bf4[i][2]);
                mma16816(acc[8 + i * 2 + 1], a1f, bf4[i][1], bf4[i][3]);
            }
        }
        __syncthreads();
        if (c < 3)      stage_chunk(c + 2);
        else if (c == 3) stage_w2();
    }

    // ---------------- gate -> z into buf1 D region (fp16) --------------------
    #pragma unroll
    for (int mf = 0; mf < 2; ++mf) {
        const int tr0 = mbase + mf * 16 + r;
        #pragma unroll
        for (int i = 0; i < 4; ++i) {
            #pragma unroll
            for (int p = 0; p < 2; ++p) {
                const int j = (wn * 4 + i) * 8 + 2 * q + p;
                const float ba = sbd[j], bb = sbd[64 + j];
                const float* a = acc[(mf * 4 + i) * 2 + p];
                #pragma unroll
                for (int h = 0; h < 2; ++h) {
                    float xa = a[h * 2 + 0] + ba;
                    float xb = a[h * 2 + 1] + bb;
                    float e2 = __expf(-2.f * fabsf(xa));
                    float th = copysignf(__fdividef(1.f - e2, 1.f + e2), xa);
                    float sg = __fdividef(1.f, 1.f + __expf(-xb));
                    float z  = th * sg;
                    const int tr = tr0 + h * 8;
                    *(__half*)(smem_c + OFF_D0 + RSZ + (uint32_t)tr * STRIDE + j * 2) = __float2half(z);
                }
            }
        }
    }

    CP_WAIT0();
    __syncthreads();

    // ---------------- GEMM2: z (buf1 D) * W2^T (buf1 W) ----------------
    float acc2[16][4];
    #pragma unroll
    for (int i = 0; i < 16; ++i)
        #pragma unroll
        for (int j2 = 0; j2 < 4; ++j2) acc2[i][j2] = 0.f;

    #pragma unroll
    for (int ks = 0; ks < 4; ++ks) {
        uint32_t a0f[4], a1f[4];
        const uint32_t a0 = sb + OFF_D0 + RSZ + (uint32_t)(mbase + lrow) * STRIDE + lkoff + ks * 32;
        ldm4(a0f, a0);
        ldm4(a1f, a0 + 16 * STRIDE);
        uint32_t wf4[4][4];
        #pragma unroll
        for (int i = 0; i < 4; ++i) {
            uint32_t baddr = sb + OFF_W0 + RSZ + (uint32_t)(nbase + i * 16 + lrow) * STRIDE + lkoff + ks * 32;
            ldm4(wf4[i], baddr);
        }
        #pragma unroll
        for (int i = 0; i < 4; ++i) {
            mma16816(acc2[i * 2],         a0f, wf4[i][0], wf4[i][2]);
            mma16816(acc2[i * 2 + 1],     a0f, wf4[i][1], wf4[i][3]);
        }
        #pragma unroll
        for (int i = 0; i < 4; ++i) {
            mma16816(acc2[8 + i * 2],     a1f, wf4[i][0], wf4[i][2]);
            mma16816(acc2[8 + i * 2 + 1], a1f, wf4[i][1], wf4[i][3]);
        }
    }

    // ---------------- epilogue (warp-uniform, coalesced [t][ch]) -------------
    if (wn == 0) {                         // out-ch 0..63 -> skip
        #pragma unroll
        for (int mf = 0; mf < 2; ++mf) {
            const int trowA = t0 + mbase + mf * 16 + r;
            const int trowB = trowA + 8;
            #pragma unroll
            for (int i = 0; i < 4; ++i) {
                #pragma unroll
                for (int p = 0; p < 2; ++p) {
                    const int ch = i * 16 + p * 8 + 2 * q;
                    const float* d = acc2[(mf * 4 + i) * 2 + p];
                    float bs0 = sbd[128 + ch], bs1 = sbd[128 + ch + 1];
                    float2* p1 = (float2*)&skip[((size_t)b * TLEN + trowA) * 64 + ch];
                    float2* p2 = (float2*)&skip[((size_t)b * TLEN + trowB) * 64 + ch];
                    float2 v1 = *p1, v2 = *p2;
                    v1.x += d[0] + bs0; v1.y += d[1] + bs1;
                    v2.x += d[2] + bs0; v2.y += d[3] + bs1;
                    *p1 = v1; *p2 = v2;
                }
            }
        }
    } else {                               // out-ch 64..127 -> residual
        #pragma unroll
        for (int mf = 0; mf < 2; ++mf) {
            const int trowA = t0 + mbase + mf * 16 + r;
            const int trowB = trowA + 8;
            #pragma unroll
            for (int i = 0; i < 4; ++i) {
                #pragma unroll
                for (int p = 0; p < 2; ++p) {
                    const int ch = i * 16 + p * 8 + 2 * q;
                    const float* d = acc2[(mf * 4 + i) * 2 + p];
                    float br0 = sbd[192 + ch], br1 = sbd[192 + ch + 1];
                    size_t e1 = ((size_t)b * TLEN + trowA) * 64 + ch;
                    size_t e2 = ((size_t)b * TLEN + trowB) * 64 + ch;
                    float2 i1 = *(const float2*)&hin32[e1];
                    float2 i2 = *(const float2*)&hin32[e2];
                    float h10 = (d[0] + br0 + i1.x) * SQRT_HALF;
                    float h11 = (d[1] + br1 + i1.y) * SQRT_HALF;
                    float h20 = (d[2] + br0 + i2.x) * SQRT_HALF;
                    float h21 = (d[3] + br1 + i2.y) * SQRT_HALF;
                    *(float2*)&hout32[e1] = make_float2(h10, h11);
                    *(float2*)&hout32[e2] = make_float2(h20, h21);
                    *(uint32_t*)&hout16[e1] = packh2(h10, h11);
                    *(uint32_t*)&hout16[e2] = packh2(h20, h21);
                }
            }
        }
    }
}

// ======================= final head ==========================================
__global__ void final2(const float* __restrict__ skip,
                       const float* __restrict__ Wl1, const float* __restrict__ bl1,
                       const float* __restrict__ Wl2, const float* __restrict__ bl2,
                       float* __restrict__ out) {
    __shared__ float tile[128 * 65];
    __shared__ float b1s[64];
    __shared__ float W2s[64];
    int tid = threadIdx.x;   // 128
    if (tid < 64) { b1s[tid] = bl1[tid]; W2s[tid] = Wl2[tid]; }
    int t0 = (blockIdx.x & 255) * 128;
    int b  = blockIdx.x >> 8;
    for (int i = tid; i < 128 * 64; i += 128) {
        int rr = i >> 6, cc = i & 63;
        tile[rr * 65 + cc] = skip[((size_t)b * TLEN + t0) * 64 + i];
    }
    __syncthreads();
    float s1[64];
    #pragma unroll 8
    for (int j = 0; j < 64; ++j)
        s1[j] = fmaxf(tile[tid * 65 + j] * SQRT_INV_L, 0.f);
    float y2 = bl2[0];
    for (int o = 0; o < 64; ++o) {
        float a = b1s[o];
        #pragma unroll 8
        for (int j = 0; j < 64; ++j) a += Wl1[o * 64 + j] * s1[j];
        y2 += W2s[o] * fmaxf(a, 0.f);
    }
    out[(size_t)b * TLEN + t0 + tid] = y2;
}

// ======================= launch ==============================================
extern "C" void kernel_launch(void* const* d_in, const int* in_sizes, int n_in,
                              void* d_out, int out_size)
{
    const float* x       = (const float*)d_in[0];
    const float* c       = (const float*)d_in[1];
    const float* W_first = (const float*)d_in[2];
    const float* b_first = (const float*)d_in[3];
    const float* W_cin   = (const float*)d_in[4];
    const float* W_up    = (const float*)d_in[5];
    const float* Wd      = (const float*)d_in[6];
    const float* bd      = (const float*)d_in[7];
    const float* Wa      = (const float*)d_in[8];
    const float* Ws      = (const float*)d_in[9];
    const float* bs      = (const float*)d_in[10];
    const float* Wr      = (const float*)d_in[11];
    const float* br      = (const float*)d_in[12];
    const float* Wl1     = (const float*)d_in[13];
    const float* bl1     = (const float*)d_in[14];
    const float* Wl2     = (const float*)d_in[15];
    const float* bl2     = (const float*)d_in[16];
    float* out = (float*)d_out;

    float *skip, *h32a, *h32b;
    __half *h16a, *h16b, *c16, *Wg16, *W216;
    cudaGetSymbolAddress((void**)&skip, g_skip);
    cudaGetSymbolAddress((void**)&h32a, g_h32a);
    cudaGetSymbolAddress((void**)&h32b, g_h32b);
    cudaGetSymbolAddress((void**)&h16a, g_h16a);
    cudaGetSymbolAddress((void**)&h16b, g_h16b);
    cudaGetSymbolAddress((void**)&c16,  g_c16);
    cudaGetSymbolAddress((void**)&Wg16, g_Wg16);
    cudaGetSymbolAddress((void**)&W216, g_W216);

    const int COND_SMEM = (80 * 6 + 80 * 8 + 80 * 8 + 80 * 14 + 80 * 36 + 80 * 128) * 4;
    cudaFuncSetAttribute(cond_fused, cudaFuncAttributeMaxDynamicSharedMemorySize, COND_SMEM);
    cudaFuncSetAttribute(layer_mma, cudaFuncAttributeMaxDynamicSharedMemorySize, SMEM_NEED);

    {
        dim3 grid(TLEN / 128, NB);
        cond_fused<<<grid, 256, COND_SMEM>>>(c, W_cin, W_up, c16);
    }
    {
        int N = NLAYERS * 5 * 128 * 64 + NLAYERS * 128 * 64;
        prepack_w<<<(N + 255) / 256, 256>>>(Wd, Wa, Ws, Wr, Wg16, W216);
    }
    {
        int N = NB * TLEN * RC;
        first_pack<<<(N + 255) / 256, 256>>>(x, W_first, b_first, h32a, h16a, skip);
    }
    float *hi32 = h32a, *ho32 = h32b;
    __half *hi16 = h16a, *ho16 = h16b;
    dim3 grid(TLEN / 128, NB);
    for (int i = 0; i < NLAYERS; ++i) {
        int d = 1 << (i % 10);
        layer_mma<<<grid, 256, SMEM_NEED>>>(i, d, hi32, ho32, hi16, ho16,
                                            c16, skip, Wg16, W216, bd, bs, br);
        { float* t = hi32; hi32 = ho32; ho32 = t; }
        { __half* t = hi16; hi16 = ho16; ho16 = t; }
    }
    final2<<<NB * (TLEN / 128), 128>>>(skip, Wl1, bl1, Wl2, bl2, out);
}